// round 7
// baseline (speedup 1.0000x reference)
#include <cuda_runtime.h>
#include <math.h>
#include <stdint.h>

#define L_SEQ   2048
#define D_MODEL 1024
#define N_HEADS 16
#define D_HEAD  64
#define BATCH   2
#define BH      (BATCH * N_HEADS)     /* 32  */
#define M_ROWS  (BATCH * L_SEQ)       /* 4096 */

/* ------------ scratch (static device globals: no allocation allowed) ------ */
__device__ __align__(16) float g_q[BH * L_SEQ * D_HEAD];
__device__ __align__(16) float g_k[BH * L_SEQ * D_HEAD];
__device__ __align__(16) float g_v[BH * L_SEQ * D_HEAD];
__device__ __align__(16) float g_x[(size_t)M_ROWS * D_MODEL];

/* =========================== helpers ==================================== */
__device__ __forceinline__ uint32_t smem_u32(const void* p)
{
    uint32_t a;
    asm("{ .reg .u64 t; cvta.to.shared.u64 t, %1; cvt.u32.u64 %0, t; }"
        : "=r"(a) : "l"(p));
    return a;
}

__device__ __forceinline__ void cp_async16(uint32_t dst, const void* src)
{
    asm volatile("cp.async.cg.shared.global [%0], [%1], 16;"
                 :: "r"(dst), "l"(src) : "memory");
}
__device__ __forceinline__ void cp_commit()
{
    asm volatile("cp.async.commit_group;" ::: "memory");
}
__device__ __forceinline__ void cp_wait0()
{
    asm volatile("cp.async.wait_group 0;" ::: "memory");
}

__device__ __forceinline__ void mma_tf32(float* d, const uint32_t* a, const uint32_t* b)
{
    asm volatile(
        "mma.sync.aligned.m16n8k8.row.col.f32.tf32.tf32.f32 "
        "{%0,%1,%2,%3}, {%4,%5,%6,%7}, {%8,%9}, {%0,%1,%2,%3};"
        : "+f"(d[0]), "+f"(d[1]), "+f"(d[2]), "+f"(d[3])
        : "r"(a[0]), "r"(a[1]), "r"(a[2]), "r"(a[3]),
          "r"(b[0]), "r"(b[1]));
}

/* tf32-consistent value: zero the 13 mantissa bits mma ignores */
__device__ __forceinline__ float trunc_tf32(uint32_t bits)
{
    return __uint_as_float(bits & 0xFFFFE000u);
}

/* fragment layouts (words). KT = number of 8-wide k-tiles per row.
 * A-frag (scalar/cp.async): block=(m>>4)*KT+(k>>3) [128 w];
 *   word = block*128 + reg*32 + fraglane,
 *   reg=((k>>2)&1)*2+((m>>3)&1), fraglane=((m&7)<<2|(k&3)) ^ xorswz
 * B-frag (scalar/cp.async): block=(n>>3)*KT+(k>>3) [64 w];
 *   word = block*64 + reg*32 + fraglane, reg=(k>>2)&1,
 *   fraglane=((n&7)<<2|(k&3)) ^ xorswz                                    */
__device__ __forceinline__ int offA(int m, int k, int KT)
{
    return ((m >> 4) * KT + (k >> 3)) * 128
         + (((k >> 2) & 1) * 2 + ((m >> 3) & 1)) * 32
         + ((((m & 7) << 2) | (k & 3)) ^ ((((k >> 3) & 7)) << 2));
}
__device__ __forceinline__ int offB(int n, int k, int KT)
{
    return ((n >> 3) * KT + (k >> 3)) * 64
         + (((k >> 2) & 1)) * 32
         + ((((n & 7) << 2) | (k & 3)) ^ ((((n >> 3) & 7) ^ ((k >> 3) & 7)) << 2));
}
/* vectorized B-frag for V (KT=16): word = block*64 + fraglane*2 + reg */
__device__ __forceinline__ int offBv(int n, int k)
{
    return (((n >> 3) * 16 + (k >> 3)) * 64)
         + (((n & 7) * 4 + (k & 3)) * 2) + ((k >> 2) & 1);
}

/* ===========================================================================
 * tf32 GEMM: C = A @ W^T (+bias). 256 thr, 8 warps (2m x 4n), warp 64x32.
 * cp.async double-buffered straight into fragment layout; raw fp32 (tf32
 * truncation). 2 CTAs/SM -> 1 wave.
 * ========================================================================= */
#define GEMM_SMEM_BYTES 65536

__global__ __launch_bounds__(256, 2)
void gemm_mma(const float* __restrict__ A, const float* __restrict__ W,
              float* __restrict__ C, const float* __restrict__ bias,
              int head_mode)
{
    extern __shared__ __align__(16) uint32_t smg[];
    uint32_t* As = smg;           /* [2][4096] */
    uint32_t* Bs = smg + 8192;    /* [2][4096] */
    const uint32_t aB = smem_u32(As);
    const uint32_t bB = smem_u32(Bs);

    const int tid = threadIdx.x;
    const int lane = tid & 31;
    const int wid = tid >> 5;
    const int warp_m = wid >> 2;   /* 0..1 */
    const int warp_n = wid & 3;    /* 0..3 */
    const int m0 = blockIdx.y * 128, n0 = blockIdx.x * 128;

    const int cc = tid & 7;
    const int r0 = tid >> 3;       /* 0..31; rows r0 + 32*i */

    int stA[4], stB[4];
#pragma unroll
    for (int i = 0; i < 4; ++i) {
        int rr = r0 + 32 * i;
        stA[i] = (((rr >> 4) * 4 + (cc >> 1)) * 128)
               + ((cc & 1) * 2 + ((rr >> 3) & 1)) * 32 + (rr & 7) * 4;
        stB[i] = (((rr >> 3) * 4 + (cc >> 1)) * 64)
               + (cc & 1) * 32 + (rr & 7) * 4;
    }

    const float* pA = A + (size_t)(m0 + r0) * D_MODEL + cc * 4;
    const float* pB = W + (size_t)(n0 + r0) * D_MODEL + cc * 4;

    /* prologue: tile 0 into buffer 0 */
#pragma unroll
    for (int i = 0; i < 4; ++i) {
        cp_async16(aB + stA[i] * 4, pA + (size_t)i * 32 * D_MODEL);
        cp_async16(bB + stB[i] * 4, pB + (size_t)i * 32 * D_MODEL);
    }
    cp_commit();

    float acc[4][4][4];
#pragma unroll
    for (int a = 0; a < 4; ++a)
#pragma unroll
        for (int b = 0; b < 4; ++b)
#pragma unroll
            for (int c = 0; c < 4; ++c) acc[a][b][c] = 0.f;

    for (int t = 0; t < 32; ++t) {
        cp_wait0();
        __syncthreads();
        const int buf = t & 1;

        if (t < 31) {
            const float* qA = pA + (t + 1) * 32;
            const float* qB = pB + (t + 1) * 32;
            const uint32_t ob = (uint32_t)(buf ^ 1) * 16384u;
#pragma unroll
            for (int i = 0; i < 4; ++i) {
                cp_async16(aB + ob + stA[i] * 4, qA + (size_t)i * 32 * D_MODEL);
                cp_async16(bB + ob + stB[i] * 4, qB + (size_t)i * 32 * D_MODEL);
            }
            cp_commit();
        }

        const uint32_t* Ab = As + buf * 4096;
        const uint32_t* Bb = Bs + buf * 4096;
#pragma unroll
        for (int ks = 0; ks < 4; ++ks) {
            uint32_t af[4][4], bf[4][2];
#pragma unroll
            for (int mt = 0; mt < 4; ++mt) {
                int base = ((warp_m * 4 + mt) * 4 + ks) * 128 + lane;
                af[mt][0] = Ab[base];
                af[mt][1] = Ab[base + 32];
                af[mt][2] = Ab[base + 64];
                af[mt][3] = Ab[base + 96];
            }
#pragma unroll
            for (int nt = 0; nt < 4; ++nt) {
                int base = ((warp_n * 4 + nt) * 4 + ks) * 64 + lane;
                bf[nt][0] = Bb[base];
                bf[nt][1] = Bb[base + 32];
            }
#pragma unroll
            for (int mt = 0; mt < 4; ++mt)
#pragma unroll
                for (int nt = 0; nt < 4; ++nt)
                    mma_tf32(acc[mt][nt], af[mt], bf[nt]);
        }
    }

    /* ------------------------------ epilogue ----------------------------- */
    const int row_q = lane >> 2;
    const int col_q = (lane & 3) * 2;

    if (head_mode) {
#pragma unroll
        for (int mt = 0; mt < 4; ++mt)
#pragma unroll
            for (int nt = 0; nt < 4; ++nt) {
                int m = m0 + warp_m * 64 + mt * 16 + row_q;
                int n = n0 + warp_n * 32 + nt * 8 + col_q;
                int h = n >> 6, dh = n & 63;
                {
                    int bb = m >> 11, l = m & 2047;
                    *reinterpret_cast<float2*>(
                        &C[(((size_t)(bb * N_HEADS + h) * L_SEQ + l) << 6) + dh])
                        = make_float2(acc[mt][nt][0], acc[mt][nt][1]);
                }
                {
                    int m2 = m + 8;
                    int bb = m2 >> 11, l = m2 & 2047;
                    *reinterpret_cast<float2*>(
                        &C[(((size_t)(bb * N_HEADS + h) * L_SEQ + l) << 6) + dh])
                        = make_float2(acc[mt][nt][2], acc[mt][nt][3]);
                }
            }
    } else {
#pragma unroll
        for (int mt = 0; mt < 4; ++mt)
#pragma unroll
            for (int nt = 0; nt < 4; ++nt) {
                int m = m0 + warp_m * 64 + mt * 16 + row_q;
                int n = n0 + warp_n * 32 + nt * 8 + col_q;
                float2 bv = *reinterpret_cast<const float2*>(&bias[n]);
                *reinterpret_cast<float2*>(&C[(size_t)m * D_MODEL + n])
                    = make_float2(acc[mt][nt][0] + bv.x, acc[mt][nt][1] + bv.y);
                *reinterpret_cast<float2*>(&C[(size_t)(m + 8) * D_MODEL + n])
                    = make_float2(acc[mt][nt][2] + bv.x, acc[mt][nt][3] + bv.y);
            }
    }
}

/* ===========================================================================
 * Euclidean flash-attention, tensor cores + cp.async pipeline. 512 threads.
 * Q/K cp.async direct into fragment smem; V cp.async to raw staging then
 * transposed into vectorized B-frag; P stored in vectorized A-frag.
 * K(t+1)/V(t+1) prefetched during compute of t.
 * SMEM words: Qf 8192 | Kf 8192 | Vf 8192 | Pf 16384 | Vraw 8192 | q2/k2/rs 768
 * ========================================================================= */
#define ATT_SMEM_WORDS (8192 * 3 + 16384 + 8192 + 128 + 128 + 512)
#define ATT_SMEM_BYTES (ATT_SMEM_WORDS * 4)

__global__ __launch_bounds__(512, 1)
void attn_mma(const float* __restrict__ Qh, const float* __restrict__ Kh,
              const float* __restrict__ Vh, float* __restrict__ Xout)
{
    extern __shared__ __align__(16) uint32_t smw[];
    uint32_t* Qf   = smw;                       /* A-frag KT=8          */
    uint32_t* Kf   = smw + 8192;                /* B-frag KT=8          */
    uint32_t* Vf   = smw + 16384;               /* B-frag KT=16, vector */
    uint32_t* Pf   = smw + 24576;               /* A-frag KT=16, vector */
    uint32_t* Vraw = smw + 40960;               /* raw [128][64] f32    */
    float* q2 = (float*)(smw + 49152);          /* [128]  */
    float* k2 = q2 + 128;                       /* [128]  */
    float* rs = k2 + 128;                       /* [4][128] */

    const uint32_t qfB = smem_u32(Qf);
    const uint32_t kfB = smem_u32(Kf);
    const uint32_t vrB = smem_u32(Vraw);

    const int tid  = threadIdx.x;
    const int lane = tid & 31;
    const int wid  = tid >> 5;
    const int warp_m  = wid >> 2;       /* S phase: 4m x 4n  */
    const int warp_n  = wid & 3;
    const int warp_m2 = wid >> 1;       /* PV phase: 8m x 2n */
    const int warp_n2 = wid & 1;
    const int bh = blockIdx.y;
    const int q0 = blockIdx.x * 128;

    const float* Qg = Qh + ((size_t)bh * L_SEQ + q0) * D_HEAD;
    const float* Kg = Kh + (size_t)bh * L_SEQ * D_HEAD;
    const float* Vg = Vh + (size_t)bh * L_SEQ * D_HEAD;

    /* ---- prologue: Q, K(0), Vraw(0) via cp.async ------------------------- */
#pragma unroll
    for (int it = 0; it < 4; ++it) {
        int idx = it * 512 + tid;          /* 0..2047 */
        int m = idx >> 4, k0 = (idx & 15) * 4;
        cp_async16(qfB + offA(m, k0, 8) * 4, Qg + m * D_HEAD + k0);
        cp_async16(kfB + offB(m, k0, 8) * 4, Kg + m * D_HEAD + k0);
        cp_async16(vrB + idx * 16, Vg + idx * 4);
    }
    cp_commit();
    cp_wait0();
    __syncthreads();

    /* ---- q2 from truncated Q values --------------------------------------- */
#pragma unroll
    for (int it = 0; it < 4; ++it) {
        int idx = it * 512 + tid;
        int m = idx >> 4, c4 = idx & 15;
        uint4 u = *reinterpret_cast<const uint4*>(&Qf[offA(m, c4 * 4, 8)]);
        float a = trunc_tf32(u.x), b = trunc_tf32(u.y);
        float c = trunc_tf32(u.z), d = trunc_tf32(u.w);
        float part = a * a + b * b + c * c + d * d;
        part += __shfl_xor_sync(0xffffffffu, part, 1);
        part += __shfl_xor_sync(0xffffffffu, part, 2);
        part += __shfl_xor_sync(0xffffffffu, part, 4);
        part += __shfl_xor_sync(0xffffffffu, part, 8);
        if (c4 == 0) q2[m] = part;
    }

    float oacc[4][4];
#pragma unroll
    for (int b = 0; b < 4; ++b)
#pragma unroll
        for (int c = 0; c < 4; ++c) oacc[b][c] = 0.f;
    float rsum[2][2];
    rsum[0][0] = rsum[0][1] = rsum[1][0] = rsum[1][1] = 0.f;

    for (int kt = 0; kt < 16; ++kt) {
        /* ---- transpose V(kt) into Vf; k2(kt) from Kf ---------------------- */
#pragma unroll
        for (int it = 0; it < 4; ++it) {
            int idx = it * 512 + tid;
            int n = idx >> 4, c4 = idx & 15, k0 = c4 * 4;

            float4 vv = *reinterpret_cast<const float4*>(&Vraw[idx * 4]);
            Vf[offBv(k0 + 0, n)] = __float_as_uint(vv.x);
            Vf[offBv(k0 + 1, n)] = __float_as_uint(vv.y);
            Vf[offBv(k0 + 2, n)] = __float_as_uint(vv.z);
            Vf[offBv(k0 + 3, n)] = __float_as_uint(vv.w);

            uint4 u = *reinterpret_cast<const uint4*>(&Kf[offB(n, k0, 8)]);
            float a = trunc_tf32(u.x), b = trunc_tf32(u.y);
            float c = trunc_tf32(u.z), d = trunc_tf32(u.w);
            float part = a * a + b * b + c * c + d * d;
            part += __shfl_xor_sync(0xffffffffu, part, 1);
            part += __shfl_xor_sync(0xffffffffu, part, 2);
            part += __shfl_xor_sync(0xffffffffu, part, 4);
            part += __shfl_xor_sync(0xffffffffu, part, 8);
            if (c4 == 0) k2[n] = part;
        }
        __syncthreads();

        /* prefetch V(kt+1) into Vraw (reads done above + barrier) */
        if (kt < 15) {
#pragma unroll
            for (int it = 0; it < 4; ++it) {
                int idx = it * 512 + tid;
                cp_async16(vrB + idx * 16, Vg + (size_t)(kt + 1) * 8192 + idx * 4);
            }
            cp_commit();
        }

        /* ---- S = Q.K^T (warp tile 32x32) ---------------------------------- */
        float sacc[2][4][4];
#pragma unroll
        for (int a = 0; a < 2; ++a)
#pragma unroll
            for (int b = 0; b < 4; ++b)
#pragma unroll
                for (int c = 0; c < 4; ++c) sacc[a][b][c] = 0.f;

#pragma unroll
        for (int ks = 0; ks < 8; ++ks) {
            uint32_t af[2][4], bf[4][2];
#pragma unroll
            for (int mt = 0; mt < 2; ++mt) {
                int base = ((warp_m * 2 + mt) * 8 + ks) * 128
                         + (lane ^ ((ks & 7) << 2));
                af[mt][0] = Qf[base];
                af[mt][1] = Qf[base + 32];
                af[mt][2] = Qf[base + 64];
                af[mt][3] = Qf[base + 96];
            }
#pragma unroll
            for (int nt = 0; nt < 4; ++nt) {
                int Nt = warp_n * 4 + nt;
                int base = (Nt * 8 + ks) * 64
                         + (lane ^ ((((Nt & 7) ^ (ks & 7))) << 2));
                bf[nt][0] = Kf[base];
                bf[nt][1] = Kf[base + 32];
            }
#pragma unroll
            for (int mt = 0; mt < 2; ++mt)
#pragma unroll
                for (int nt = 0; nt < 4; ++nt)
                    mma_tf32(sacc[mt][nt], af[mt], bf[nt]);
        }

        /* ---- euclid weights + exp + P stage (vector A-frag) --------------- */
#pragma unroll
        for (int mt = 0; mt < 2; ++mt) {
            int m1 = warp_m * 32 + mt * 16 + (lane >> 2);
            float q2a = q2[m1], q2b = q2[m1 + 8];
#pragma unroll
            for (int nt = 0; nt < 4; ++nt) {
                int c0 = warp_n * 32 + nt * 8 + (lane & 3) * 2;
                float k2a = k2[c0], k2b = k2[c0 + 1];
                float d0 = fmaxf(fmaf(sacc[mt][nt][0], -2.f, q2a + k2a), 1e-24f);
                float d1 = fmaxf(fmaf(sacc[mt][nt][1], -2.f, q2a + k2b), 1e-24f);
                float d2 = fmaxf(fmaf(sacc[mt][nt][2], -2.f, q2b + k2a), 1e-24f);
                float d3 = fmaxf(fmaf(sacc[mt][nt][3], -2.f, q2b + k2b), 1e-24f);
                /* exp(8*rsqrt(d)) = exp2(11.5415603*rsqrt(d)), clamp 101 */
                float p0 = exp2f(fminf(rsqrtf(d0) * 11.5415603f, 101.f));
                float p1 = exp2f(fminf(rsqrtf(d1) * 11.5415603f, 101.f));
                float p2 = exp2f(fminf(rsqrtf(d2) * 11.5415603f, 101.f));
                float p3 = exp2f(fminf(rsqrtf(d3) * 11.5415603f, 101.f));
                rsum[mt][0] += p0 + p1;
                rsum[mt][1] += p2 + p3;
                int w0 = ((m1 >> 4) * 16 + (c0 >> 3)) * 128
                       + ((lane >> 2) * 4 + (c0 & 3)) * 4 + ((c0 >> 2) & 1) * 2;
                *reinterpret_cast<float2*>((float*)&Pf[w0])     = make_float2(p0, p2);
                *reinterpret_cast<float2*>((float*)&Pf[w0 + 4]) = make_float2(p1, p3);
            }
        }
        __syncthreads();

        /* prefetch K(kt+1) straight into Kf (S-phase reads done + barrier) */
        if (kt < 15) {
#pragma unroll
            for (int it = 0; it < 4; ++it) {
                int idx = it * 512 + tid;
                int m = idx >> 4, k0 = (idx & 15) * 4;
                cp_async16(kfB + offB(m, k0, 8) * 4,
                           Kg + (size_t)(kt + 1) * 8192 + m * D_HEAD + k0);
            }
            cp_commit();
        }

        /* ---- O += P @ V (warp tile 16x32, K=128, vector LDS) --------------- */
#pragma unroll 4
        for (int ks2 = 0; ks2 < 16; ++ks2) {
            uint32_t pf[4], vf[4][2];
            {
                uint4 pu = *reinterpret_cast<const uint4*>(
                    &Pf[(warp_m2 * 16 + ks2) * 128 + lane * 4]);
                pf[0] = pu.x; pf[1] = pu.y; pf[2] = pu.z; pf[3] = pu.w;
            }
#pragma unroll
            for (int nt2 = 0; nt2 < 4; ++nt2) {
                int Nt2 = warp_n2 * 4 + nt2;
                uint2 vu = *reinterpret_cast<const uint2*>(
                    &Vf[(Nt2 * 16 + ks2) * 64 + lane * 2]);
                vf[nt2][0] = vu.x; vf[nt2][1] = vu.y;
            }
#pragma unroll
            for (int nt2 = 0; nt2 < 4; ++nt2)
                mma_tf32(oacc[nt2], pf, vf[nt2]);
        }
        if (kt < 15) cp_wait0();
        __syncthreads();
    }

    /* ---- cross-warp row-sum reduce ----------------------------------------- */
#pragma unroll
    for (int mt = 0; mt < 2; ++mt)
#pragma unroll
        for (int rh = 0; rh < 2; ++rh) {
            float r = rsum[mt][rh];
            r += __shfl_xor_sync(0xffffffffu, r, 1);
            r += __shfl_xor_sync(0xffffffffu, r, 2);
            if ((lane & 3) == 0)
                rs[warp_n * 128 + warp_m * 32 + mt * 16 + rh * 8 + (lane >> 2)] = r;
        }
    __syncthreads();

    /* ---- normalize + writeback [B,L,D] -------------------------------------- */
    const int b = bh >> 4, h = bh & 15;
    {
        int m = warp_m2 * 16 + (lane >> 2);
        float s1 = rs[m] + rs[128 + m] + rs[256 + m] + rs[384 + m];
        float s2 = rs[m + 8] + rs[128 + m + 8] + rs[256 + m + 8] + rs[384 + m + 8];
        float inv1 = __fdividef(1.f, s1);
        float inv2 = __fdividef(1.f, s2);
#pragma unroll
        for (int nt2 = 0; nt2 < 4; ++nt2) {
            int c = warp_n2 * 32 + nt2 * 8 + (lane & 3) * 2;
            size_t b1 = ((size_t)(b * L_SEQ + q0 + m)) * D_MODEL + h * 64 + c;
            size_t b2 = ((size_t)(b * L_SEQ + q0 + m + 8)) * D_MODEL + h * 64 + c;
            *reinterpret_cast<float2*>(&Xout[b1])
                = make_float2(oacc[nt2][0] * inv1, oacc[nt2][1] * inv1);
            *reinterpret_cast<float2*>(&Xout[b2])
                = make_float2(oacc[nt2][2] * inv2, oacc[nt2][3] * inv2);
        }
    }
}

/* ========================================================================= */
extern "C" void kernel_launch(void* const* d_in, const int* in_sizes, int n_in,
                              void* d_out, int out_size)
{
    (void)in_sizes; (void)n_in; (void)out_size;
    const float* query = (const float*)d_in[0];
    const float* key_  = (const float*)d_in[1];
    const float* value = (const float*)d_in[2];
    const float* Wq    = (const float*)d_in[3];
    const float* Wk    = (const float*)d_in[4];
    const float* Wv    = (const float*)d_in[5];
    const float* Wo    = (const float*)d_in[6];
    const float* bo    = (const float*)d_in[7];
    float* out = (float*)d_out;

    float *qp, *kp, *vp, *xp;
    cudaGetSymbolAddress((void**)&qp, g_q);
    cudaGetSymbolAddress((void**)&kp, g_k);
    cudaGetSymbolAddress((void**)&vp, g_v);
    cudaGetSymbolAddress((void**)&xp, g_x);

    cudaFuncSetAttribute(gemm_mma, cudaFuncAttributeMaxDynamicSharedMemorySize,
                         GEMM_SMEM_BYTES);
    cudaFuncSetAttribute(attn_mma, cudaFuncAttributeMaxDynamicSharedMemorySize,
                         ATT_SMEM_BYTES);

    dim3 ggrid(D_MODEL / 128, M_ROWS / 128);
    gemm_mma<<<ggrid, 256, GEMM_SMEM_BYTES>>>(query, Wq, qp, nullptr, 1);
    gemm_mma<<<ggrid, 256, GEMM_SMEM_BYTES>>>(key_,  Wk, kp, nullptr, 1);
    gemm_mma<<<ggrid, 256, GEMM_SMEM_BYTES>>>(value, Wv, vp, nullptr, 1);

    attn_mma<<<dim3(16, BH), 512, ATT_SMEM_BYTES>>>(qp, kp, vp, xp);

    gemm_mma<<<ggrid, 256, GEMM_SMEM_BYTES>>>(xp, Wo, out, bo, 0);
}

// round 8
// speedup vs baseline: 1.2344x; 1.2344x over previous
#include <cuda_runtime.h>
#include <math.h>
#include <stdint.h>

#define L_SEQ   2048
#define D_MODEL 1024
#define N_HEADS 16
#define D_HEAD  64
#define BATCH   2
#define BH      (BATCH * N_HEADS)     /* 32  */
#define M_ROWS  (BATCH * L_SEQ)       /* 4096 */

/* ------------ scratch (static device globals: no allocation allowed) ------ */
__device__ __align__(16) float g_q[BH * L_SEQ * D_HEAD];
__device__ __align__(16) float g_k[BH * L_SEQ * D_HEAD];
__device__ __align__(16) float g_v[BH * L_SEQ * D_HEAD];
__device__ __align__(16) float g_x[(size_t)M_ROWS * D_MODEL];

/* =========================== mma.sync helpers ============================ */
__device__ __forceinline__ uint32_t f2tf32(float x)
{
    uint32_t r;
    asm("cvt.rna.tf32.f32 %0, %1;" : "=r"(r) : "f"(x));
    return r;
}

__device__ __forceinline__ uint4 cvt4(float4 v)
{
    return make_uint4(f2tf32(v.x), f2tf32(v.y), f2tf32(v.z), f2tf32(v.w));
}

__device__ __forceinline__ void mma_tf32(float* d, const uint32_t* a, const uint32_t* b)
{
    asm volatile(
        "mma.sync.aligned.m16n8k8.row.col.f32.tf32.tf32.f32 "
        "{%0,%1,%2,%3}, {%4,%5,%6,%7}, {%8,%9}, {%0,%1,%2,%3};"
        : "+f"(d[0]), "+f"(d[1]), "+f"(d[2]), "+f"(d[3])
        : "r"(a[0]), "r"(a[1]), "r"(a[2]), "r"(a[3]),
          "r"(b[0]), "r"(b[1]));
}

/* ===========================================================================
 * tf32 GEMM — the R4/R5 version verbatim (RNA cvt, register-staged double
 * buffer, 256 thr, 8 warps 2m x 4n, warp tile 64x32). Known ~117 us each.
 * ========================================================================= */
#define GEMM_SMEM_BYTES 65536

__global__ __launch_bounds__(256)
void gemm_mma(const float* __restrict__ A, const float* __restrict__ W,
              float* __restrict__ C, const float* __restrict__ bias,
              int head_mode)
{
    extern __shared__ __align__(16) uint32_t smg[];
    uint32_t* As = smg;           /* [2][4096] */
    uint32_t* Bs = smg + 8192;    /* [2][4096] */

    const int tid = threadIdx.x;
    const int lane = tid & 31;
    const int wid = tid >> 5;
    const int warp_m = wid >> 2;
    const int warp_n = wid & 3;
    const int m0 = blockIdx.y * 128, n0 = blockIdx.x * 128;

    const int cc = tid & 7;
    const int r0 = tid >> 3;

    int stA[4], stB[4];
#pragma unroll
    for (int i = 0; i < 4; ++i) {
        int rr = r0 + 32 * i;
        stA[i] = (((rr >> 4) * 4 + (cc >> 1)) * 128)
               + ((cc & 1) * 2 + ((rr >> 3) & 1)) * 32 + (rr & 7) * 4;
        stB[i] = (((rr >> 3) * 4 + (cc >> 1)) * 64)
               + (cc & 1) * 32 + (rr & 7) * 4;
    }

    float acc[4][4][4];
#pragma unroll
    for (int a = 0; a < 4; ++a)
#pragma unroll
        for (int b = 0; b < 4; ++b)
#pragma unroll
            for (int c = 0; c < 4; ++c) acc[a][b][c] = 0.f;

    const float* pA = A + (size_t)(m0 + r0) * D_MODEL + cc * 4;
    const float* pB = W + (size_t)(n0 + r0) * D_MODEL + cc * 4;

    float4 ga[4], gb[4];
#pragma unroll
    for (int i = 0; i < 4; ++i) {
        ga[i] = *reinterpret_cast<const float4*>(pA + (size_t)i * 32 * D_MODEL);
        gb[i] = *reinterpret_cast<const float4*>(pB + (size_t)i * 32 * D_MODEL);
    }
#pragma unroll
    for (int i = 0; i < 4; ++i) {
        *reinterpret_cast<uint4*>(&As[stA[i]]) = cvt4(ga[i]);
        *reinterpret_cast<uint4*>(&Bs[stB[i]]) = cvt4(gb[i]);
    }
    __syncthreads();

    for (int t = 0; t < 32; ++t) {
        const int buf = t & 1;
        if (t < 31) {
            const float* qA = pA + (t + 1) * 32;
            const float* qB = pB + (t + 1) * 32;
#pragma unroll
            for (int i = 0; i < 4; ++i) {
                ga[i] = *reinterpret_cast<const float4*>(qA + (size_t)i * 32 * D_MODEL);
                gb[i] = *reinterpret_cast<const float4*>(qB + (size_t)i * 32 * D_MODEL);
            }
        }
        const uint32_t* Ab = As + buf * 4096;
        const uint32_t* Bb = Bs + buf * 4096;
#pragma unroll
        for (int ks = 0; ks < 4; ++ks) {
            uint32_t af[4][4], bf[4][2];
#pragma unroll
            for (int mt = 0; mt < 4; ++mt) {
                int base = ((warp_m * 4 + mt) * 4 + ks) * 128 + lane;
                af[mt][0] = Ab[base];
                af[mt][1] = Ab[base + 32];
                af[mt][2] = Ab[base + 64];
                af[mt][3] = Ab[base + 96];
            }
#pragma unroll
            for (int nt = 0; nt < 4; ++nt) {
                int base = ((warp_n * 4 + nt) * 4 + ks) * 64 + lane;
                bf[nt][0] = Bb[base];
                bf[nt][1] = Bb[base + 32];
            }
#pragma unroll
            for (int mt = 0; mt < 4; ++mt)
#pragma unroll
                for (int nt = 0; nt < 4; ++nt)
                    mma_tf32(acc[mt][nt], af[mt], bf[nt]);
        }
        if (t < 31) {
            const int ob = buf ^ 1;
#pragma unroll
            for (int i = 0; i < 4; ++i) {
                *reinterpret_cast<uint4*>(&As[ob * 4096 + stA[i]]) = cvt4(ga[i]);
                *reinterpret_cast<uint4*>(&Bs[ob * 4096 + stB[i]]) = cvt4(gb[i]);
            }
        }
        __syncthreads();
    }

    const int row_q = lane >> 2;
    const int col_q = (lane & 3) * 2;

    if (head_mode) {
#pragma unroll
        for (int mt = 0; mt < 4; ++mt)
#pragma unroll
            for (int nt = 0; nt < 4; ++nt) {
                int m = m0 + warp_m * 64 + mt * 16 + row_q;
                int n = n0 + warp_n * 32 + nt * 8 + col_q;
                int h = n >> 6, dh = n & 63;
                {
                    int bb = m >> 11, l = m & 2047;
                    *reinterpret_cast<float2*>(
                        &C[(((size_t)(bb * N_HEADS + h) * L_SEQ + l) << 6) + dh])
                        = make_float2(acc[mt][nt][0], acc[mt][nt][1]);
                }
                {
                    int m2 = m + 8;
                    int bb = m2 >> 11, l = m2 & 2047;
                    *reinterpret_cast<float2*>(
                        &C[(((size_t)(bb * N_HEADS + h) * L_SEQ + l) << 6) + dh])
                        = make_float2(acc[mt][nt][2], acc[mt][nt][3]);
                }
            }
    } else {
#pragma unroll
        for (int mt = 0; mt < 4; ++mt)
#pragma unroll
            for (int nt = 0; nt < 4; ++nt) {
                int m = m0 + warp_m * 64 + mt * 16 + row_q;
                int n = n0 + warp_n * 32 + nt * 8 + col_q;
                float2 bv = *reinterpret_cast<const float2*>(&bias[n]);
                *reinterpret_cast<float2*>(&C[(size_t)m * D_MODEL + n])
                    = make_float2(acc[mt][nt][0] + bv.x, acc[mt][nt][1] + bv.y);
                *reinterpret_cast<float2*>(&C[(size_t)(m + 8) * D_MODEL + n])
                    = make_float2(acc[mt][nt][2] + bv.x, acc[mt][nt][3] + bv.y);
            }
    }
}

/* ===========================================================================
 * Euclidean flash-attention, P-in-registers version.
 * 256 thr, 8 warps; warp = 16 q-rows x full 128 k-cols, split in 2 halves
 * of 8 S-tiles each (sacc 32 regs -> converted in place to A-fragments via
 * quad shuffles -> PV immediately). No P smem, no cross-warp reductions.
 * smem ~97KB, regs <=128 -> __launch_bounds__(256,2): 2 independent CTAs/SM.
 *
 * Layouts (words):
 *  Qf A-frag vec : block=(m>>4)*8+(k>>3); word=block*128
 *                  + ((( (m&7)*4+(k&3) ) ^ ((k>>3)&7))*4) + (m>>3) + 2*((k>>2)&1)
 *  Kf B-frag vec : block=(n>>3)*8+(k>>3);  sw=((n>>3)^(k>>3))&7
 *  Vf B-frag vec : block=(n>>3)*16+(k>>3); sw=((n>>3)^(k>>3))&7
 *                  word=block*64 + ((((n&7)*4+(k&3)) ^ sw)*2) + ((k>>2)&1)
 * ========================================================================= */
#define ATT_SMEM_WORDS (8192 * 3 + 256)
#define ATT_SMEM_BYTES (ATT_SMEM_WORDS * 4)

__global__ __launch_bounds__(256, 2)
void attn_mma(const float* __restrict__ Qh, const float* __restrict__ Kh,
              const float* __restrict__ Vh, float* __restrict__ Xout)
{
    extern __shared__ __align__(16) uint32_t smw[];
    uint32_t* Qf = smw;                 /* 8192 words */
    uint32_t* Kf = smw + 8192;          /* 8192 words */
    uint32_t* Vf = smw + 16384;         /* 8192 words */
    float* q2 = (float*)(smw + 24576);  /* [128] */
    float* k2 = q2 + 128;               /* [128] */

    const int tid  = threadIdx.x;
    const int lane = tid & 31;
    const int wid  = tid >> 5;          /* warp owns q-rows wid*16..+15 */
    const int qq   = lane & 3;
    const int bh = blockIdx.y;
    const int q0 = blockIdx.x * 128;

    const float4* Qg4 = reinterpret_cast<const float4*>(
        Qh + ((size_t)bh * L_SEQ + q0) * D_HEAD);
    const float4* Kg4 = reinterpret_cast<const float4*>(
        Kh + (size_t)bh * L_SEQ * D_HEAD);
    const float4* Vg4 = reinterpret_cast<const float4*>(
        Vh + (size_t)bh * L_SEQ * D_HEAD);

    /* ---- prologue: Q -> Qf (A-frag vec layout) + q2 ----------------------- */
#pragma unroll
    for (int it = 0; it < 8; ++it) {
        int idx = it * 256 + tid;              /* 0..2047 */
        int m = idx >> 4, c4 = idx & 15, k0 = c4 * 4;
        uint4 u = cvt4(Qg4[idx]);
        int blk = (m >> 4) * 8 + (k0 >> 3);
        int swz = (k0 >> 3) & 7;
        int rg  = ((m >> 3) & 1) + 2 * ((k0 >> 2) & 1);
        int fb  = (m & 7) * 4;
        Qf[blk * 128 + (((fb + 0) ^ swz) * 4) + rg] = u.x;
        Qf[blk * 128 + (((fb + 1) ^ swz) * 4) + rg] = u.y;
        Qf[blk * 128 + (((fb + 2) ^ swz) * 4) + rg] = u.z;
        Qf[blk * 128 + (((fb + 3) ^ swz) * 4) + rg] = u.w;
        float a = __uint_as_float(u.x), b = __uint_as_float(u.y);
        float c = __uint_as_float(u.z), d = __uint_as_float(u.w);
        float part = a * a + b * b + c * c + d * d;
        part += __shfl_xor_sync(0xffffffffu, part, 1);
        part += __shfl_xor_sync(0xffffffffu, part, 2);
        part += __shfl_xor_sync(0xffffffffu, part, 4);
        part += __shfl_xor_sync(0xffffffffu, part, 8);
        if (c4 == 0) q2[m] = part;
    }
    __syncthreads();

    const float q2a = q2[wid * 16 + (lane >> 2)];
    const float q2b = q2[wid * 16 + 8 + (lane >> 2)];

    float oacc[8][4];
#pragma unroll
    for (int b = 0; b < 8; ++b)
#pragma unroll
        for (int c = 0; c < 4; ++c) oacc[b][c] = 0.f;
    float rsum0 = 0.f, rsum1 = 0.f;

    const int h1 = (lane & ~3) | (qq >> 1);
    const int h2 = h1 + 2;

    for (int kt = 0; kt < 16; ++kt) {
        /* ---- load K,V tile kt into fragment smem + k2 --------------------- */
#pragma unroll
        for (int it = 0; it < 8; ++it) {
            int idx = it * 256 + tid;
            int r = idx >> 4, c4 = idx & 15, k0 = c4 * 4;

            /* K: row n=r, cols k0..k0+3 */
            uint4 uk = cvt4(Kg4[kt * 2048 + idx]);
            {
                int blk = (r >> 3) * 8 + (k0 >> 3);
                int sw  = ((r >> 3) ^ (k0 >> 3)) & 7;
                int rg  = (k0 >> 2) & 1;
                int fb  = (r & 7) * 4;
                Kf[blk * 64 + (((fb + 0) ^ sw) * 2) + rg] = uk.x;
                Kf[blk * 64 + (((fb + 1) ^ sw) * 2) + rg] = uk.y;
                Kf[blk * 64 + (((fb + 2) ^ sw) * 2) + rg] = uk.z;
                Kf[blk * 64 + (((fb + 3) ^ sw) * 2) + rg] = uk.w;
            }
            float a = __uint_as_float(uk.x), b = __uint_as_float(uk.y);
            float c = __uint_as_float(uk.z), d = __uint_as_float(uk.w);
            float part = a * a + b * b + c * c + d * d;
            part += __shfl_xor_sync(0xffffffffu, part, 1);
            part += __shfl_xor_sync(0xffffffffu, part, 2);
            part += __shfl_xor_sync(0xffffffffu, part, 4);
            part += __shfl_xor_sync(0xffffffffu, part, 8);
            if (c4 == 0) k2[r] = part;

            /* V: seq row s=r, dh cols d0..d0+3 -> element (n=dh, k=s) */
            uint4 uv = cvt4(Vg4[kt * 2048 + idx]);
            {
                int s = r, d0 = c4 * 4;
                int rg = (s >> 2) & 1;
                uint32_t vals[4] = { uv.x, uv.y, uv.z, uv.w };
#pragma unroll
                for (int j = 0; j < 4; ++j) {
                    int n = d0 + j;
                    int blk = (n >> 3) * 16 + (s >> 3);
                    int sw  = ((n >> 3) ^ (s >> 3)) & 7;
                    Vf[blk * 64 + (((((n & 7) * 4) + (s & 3)) ^ sw) * 2) + rg] = vals[j];
                }
            }
        }
        __syncthreads();

        /* ---- two halves of 8 S-tiles each --------------------------------- */
#pragma unroll
        for (int half = 0; half < 2; ++half) {
            float sacc[8][4];
#pragma unroll
            for (int j = 0; j < 8; ++j)
#pragma unroll
                for (int c = 0; c < 4; ++c) sacc[j][c] = 0.f;

            /* S = Q.K^T over the 8 n-tiles of this half */
#pragma unroll
            for (int ks = 0; ks < 8; ++ks) {
                uint32_t af[4];
                {
                    const uint4 u = *reinterpret_cast<const uint4*>(
                        &Qf[(wid * 8 + ks) * 128 + ((lane ^ ks) * 4)]);
                    af[0] = u.x; af[1] = u.y; af[2] = u.z; af[3] = u.w;
                }
#pragma unroll
                for (int j = 0; j < 8; ++j) {
                    int nt = half * 8 + j;
                    uint32_t bf[2];
                    const uint2 u2 = *reinterpret_cast<const uint2*>(
                        &Kf[(nt * 8 + ks) * 64 + ((lane ^ ((nt ^ ks) & 7)) * 2)]);
                    bf[0] = u2.x; bf[1] = u2.y;
                    mma_tf32(sacc[j], af, bf);
                }
            }

            /* convert: D-frag -> euclid weight -> A-frag, in place */
            uint32_t* pa = reinterpret_cast<uint32_t*>(&sacc[0][0]);
#pragma unroll
            for (int j = 0; j < 8; ++j) {
                int nt = half * 8 + j;
                float s0 = sacc[j][0], s1 = sacc[j][1];
                float s2 = sacc[j][2], s3 = sacc[j][3];
                float e, o;
                e = __shfl_sync(0xffffffffu, s0, h1);
                o = __shfl_sync(0xffffffffu, s1, h1);
                float w_rq  = (qq & 1) ? o : e;
                e = __shfl_sync(0xffffffffu, s0, h2);
                o = __shfl_sync(0xffffffffu, s1, h2);
                float w_rq4 = (qq & 1) ? o : e;
                e = __shfl_sync(0xffffffffu, s2, h1);
                o = __shfl_sync(0xffffffffu, s3, h1);
                float w_8q  = (qq & 1) ? o : e;
                e = __shfl_sync(0xffffffffu, s2, h2);
                o = __shfl_sync(0xffffffffu, s3, h2);
                float w_8q4 = (qq & 1) ? o : e;

                float k2a = k2[nt * 8 + qq];
                float k2b = k2[nt * 8 + qq + 4];
                float d0 = fmaxf(fmaf(w_rq,  -2.f, q2a + k2a), 1e-24f);
                float d1 = fmaxf(fmaf(w_8q,  -2.f, q2b + k2a), 1e-24f);
                float d2 = fmaxf(fmaf(w_rq4, -2.f, q2a + k2b), 1e-24f);
                float d3 = fmaxf(fmaf(w_8q4, -2.f, q2b + k2b), 1e-24f);
                float p0 = __expf(fminf(rsqrtf(d0) * 8.f, 70.f));
                float p1 = __expf(fminf(rsqrtf(d1) * 8.f, 70.f));
                float p2 = __expf(fminf(rsqrtf(d2) * 8.f, 70.f));
                float p3 = __expf(fminf(rsqrtf(d3) * 8.f, 70.f));
                rsum0 += p0 + p2;
                rsum1 += p1 + p3;
                pa[j * 4 + 0] = f2tf32(p0);
                pa[j * 4 + 1] = f2tf32(p1);
                pa[j * 4 + 2] = f2tf32(p2);
                pa[j * 4 + 3] = f2tf32(p3);
            }

            /* O += P.V over this half's 8 k-tiles */
#pragma unroll
            for (int j = 0; j < 8; ++j) {
                int ks2 = half * 8 + j;
#pragma unroll
                for (int nt2 = 0; nt2 < 8; ++nt2) {
                    uint32_t bf[2];
                    const uint2 u2 = *reinterpret_cast<const uint2*>(
                        &Vf[(nt2 * 16 + ks2) * 64 + ((lane ^ ((nt2 ^ ks2) & 7)) * 2)]);
                    bf[0] = u2.x; bf[1] = u2.y;
                    mma_tf32(oacc[nt2], &pa[j * 4], bf);
                }
            }
        }
        __syncthreads();
    }

    /* ---- quad-reduce row sums, normalize, write back ----------------------- */
    float r0 = rsum0, r1 = rsum1;
    r0 += __shfl_xor_sync(0xffffffffu, r0, 1);
    r0 += __shfl_xor_sync(0xffffffffu, r0, 2);
    r1 += __shfl_xor_sync(0xffffffffu, r1, 1);
    r1 += __shfl_xor_sync(0xffffffffu, r1, 2);
    const float inv1 = __fdividef(1.f, r0);
    const float inv2 = __fdividef(1.f, r1);

    const int b = bh >> 4, h = bh & 15;
    const int mrow = q0 + wid * 16 + (lane >> 2);
#pragma unroll
    for (int nt2 = 0; nt2 < 8; ++nt2) {
        int c = nt2 * 8 + qq * 2;
        size_t b1 = ((size_t)(b * L_SEQ + mrow)) * D_MODEL + h * 64 + c;
        size_t b2 = ((size_t)(b * L_SEQ + mrow + 8)) * D_MODEL + h * 64 + c;
        *reinterpret_cast<float2*>(&Xout[b1])
            = make_float2(oacc[nt2][0] * inv1, oacc[nt2][1] * inv1);
        *reinterpret_cast<float2*>(&Xout[b2])
            = make_float2(oacc[nt2][2] * inv2, oacc[nt2][3] * inv2);
    }
}

/* ========================================================================= */
extern "C" void kernel_launch(void* const* d_in, const int* in_sizes, int n_in,
                              void* d_out, int out_size)
{
    (void)in_sizes; (void)n_in; (void)out_size;
    const float* query = (const float*)d_in[0];
    const float* key_  = (const float*)d_in[1];
    const float* value = (const float*)d_in[2];
    const float* Wq    = (const float*)d_in[3];
    const float* Wk    = (const float*)d_in[4];
    const float* Wv    = (const float*)d_in[5];
    const float* Wo    = (const float*)d_in[6];
    const float* bo    = (const float*)d_in[7];
    float* out = (float*)d_out;

    float *qp, *kp, *vp, *xp;
    cudaGetSymbolAddress((void**)&qp, g_q);
    cudaGetSymbolAddress((void**)&kp, g_k);
    cudaGetSymbolAddress((void**)&vp, g_v);
    cudaGetSymbolAddress((void**)&xp, g_x);

    cudaFuncSetAttribute(gemm_mma, cudaFuncAttributeMaxDynamicSharedMemorySize,
                         GEMM_SMEM_BYTES);
    cudaFuncSetAttribute(attn_mma, cudaFuncAttributeMaxDynamicSharedMemorySize,
                         ATT_SMEM_BYTES);

    dim3 ggrid(D_MODEL / 128, M_ROWS / 128);
    gemm_mma<<<ggrid, 256, GEMM_SMEM_BYTES>>>(query, Wq, qp, nullptr, 1);
    gemm_mma<<<ggrid, 256, GEMM_SMEM_BYTES>>>(key_,  Wk, kp, nullptr, 1);
    gemm_mma<<<ggrid, 256, GEMM_SMEM_BYTES>>>(value, Wv, vp, nullptr, 1);

    attn_mma<<<dim3(16, BH), 256, ATT_SMEM_BYTES>>>(qp, kp, vp, xp);

    gemm_mma<<<ggrid, 256, GEMM_SMEM_BYTES>>>(xp, Wo, out, bo, 0);
}

// round 9
// speedup vs baseline: 2.5826x; 2.0923x over previous
#include <cuda_runtime.h>
#include <cuda_fp16.h>
#include <math.h>
#include <stdint.h>

#define L_SEQ   2048
#define D_MODEL 1024
#define N_HEADS 16
#define D_HEAD  64
#define BATCH   2
#define BH      (BATCH * N_HEADS)     /* 32  */
#define M_ROWS  (BATCH * L_SEQ)       /* 4096 */

/* ------------ scratch (static device globals: no allocation allowed) ------ */
__device__ __align__(16) float g_q[BH * L_SEQ * D_HEAD];
__device__ __align__(16) float g_k[BH * L_SEQ * D_HEAD];
__device__ __align__(16) float g_v[BH * L_SEQ * D_HEAD];
__device__ __align__(16) float g_x[(size_t)M_ROWS * D_MODEL];

/* =========================== fp16 mma helpers ============================ */
__device__ __forceinline__ uint32_t packh2(float lo, float hi)
{
    __half2 h = __floats2half2_rn(lo, hi);
    return *reinterpret_cast<uint32_t*>(&h);
}

__device__ __forceinline__ float2 unpackh2(uint32_t w)
{
    return __half22float2(*reinterpret_cast<__half2*>(&w));
}

__device__ __forceinline__ void mma_f16(float* d, const uint32_t* a, const uint32_t* b)
{
    asm volatile(
        "mma.sync.aligned.m16n8k16.row.col.f32.f16.f16.f32 "
        "{%0,%1,%2,%3}, {%4,%5,%6,%7}, {%8,%9}, {%0,%1,%2,%3};"
        : "+f"(d[0]), "+f"(d[1]), "+f"(d[2]), "+f"(d[3])
        : "r"(a[0]), "r"(a[1]), "r"(a[2]), "r"(a[3]),
          "r"(b[0]), "r"(b[1]));
}

/* fp16 fragment smem layouts (32-bit words hold half2 = 2 consecutive k):
 * A-frag m16 x k16 block = 128 words, vectorized (lane-major):
 *   word = block*128 + ((lp ^ swz) * 4) + reg
 *   lp  = (m&7)*4 + ((k>>1)&3)
 *   reg = ((k>>3)&1)*2 + ((m>>3)&1),  half = k&1
 *   -> lane l loads uint4 at ((l^swz)*4): a0..a3 exactly per PTX spec.
 * B-frag n8 x k16 block = 64 words:
 *   word = block*64 + ((lp ^ swz) * 2) + reg
 *   lp  = (n&7)*4 + ((k>>1)&3),  reg = (k>>3)&1,  half = k&1
 *   -> lane l loads uint2 at ((l^swz)*2): b0,b1.                          */

/* ===========================================================================
 * fp16 GEMM: C = A @ W^T (+bias). 256 thr, 8 warps (2m x 4n), warp 64x32,
 * BK=32 (2 k16-steps), register-staged double buffer, vector frag loads.
 * ========================================================================= */
#define GEMM_SMEM_BYTES 32768

__global__ __launch_bounds__(256)
void gemm_mma(const float* __restrict__ A, const float* __restrict__ W,
              float* __restrict__ C, const float* __restrict__ bias,
              int head_mode)
{
    extern __shared__ __align__(16) uint32_t smg[];
    uint32_t* As = smg;           /* [2][2048] */
    uint32_t* Bs = smg + 4096;    /* [2][2048] */

    const int tid = threadIdx.x;
    const int lane = tid & 31;
    const int wid = tid >> 5;
    const int warp_m = wid >> 2;
    const int warp_n = wid & 3;
    const int m0 = blockIdx.y * 128, n0 = blockIdx.x * 128;

    const int cc = tid & 7;        /* float4 col: k0c = cc*4 in the BK tile */
    const int r0 = tid >> 3;       /* rows r0 + 32*i                         */
    const int k0c = cc * 4;

    int sA[4], sB[4];
#pragma unroll
    for (int i = 0; i < 4; ++i) {
        int rr = r0 + 32 * i;
        sA[i] = ((rr >> 4) * 2 + (k0c >> 4)) * 128
              + ((rr & 7) * 4 + ((k0c >> 1) & 3)) * 4
              + ((k0c >> 3) & 1) * 2 + ((rr >> 3) & 1);
        sB[i] = ((rr >> 3) * 2 + (k0c >> 4)) * 64
              + ((rr & 7) * 4 + ((k0c >> 1) & 3)) * 2
              + ((k0c >> 3) & 1);
    }

    float acc[4][4][4];
#pragma unroll
    for (int a = 0; a < 4; ++a)
#pragma unroll
        for (int b = 0; b < 4; ++b)
#pragma unroll
            for (int c = 0; c < 4; ++c) acc[a][b][c] = 0.f;

    const float* pA = A + (size_t)(m0 + r0) * D_MODEL + k0c;
    const float* pB = W + (size_t)(n0 + r0) * D_MODEL + k0c;

    float4 ga[4], gb[4];
#pragma unroll
    for (int i = 0; i < 4; ++i) {
        ga[i] = *reinterpret_cast<const float4*>(pA + (size_t)i * 32 * D_MODEL);
        gb[i] = *reinterpret_cast<const float4*>(pB + (size_t)i * 32 * D_MODEL);
    }
#pragma unroll
    for (int i = 0; i < 4; ++i) {
        As[sA[i]]     = packh2(ga[i].x, ga[i].y);
        As[sA[i] + 4] = packh2(ga[i].z, ga[i].w);
        Bs[sB[i]]     = packh2(gb[i].x, gb[i].y);
        Bs[sB[i] + 2] = packh2(gb[i].z, gb[i].w);
    }
    __syncthreads();

    for (int t = 0; t < 32; ++t) {
        const int buf = t & 1;
        if (t < 31) {
            const float* qA = pA + (t + 1) * 32;
            const float* qB = pB + (t + 1) * 32;
#pragma unroll
            for (int i = 0; i < 4; ++i) {
                ga[i] = *reinterpret_cast<const float4*>(qA + (size_t)i * 32 * D_MODEL);
                gb[i] = *reinterpret_cast<const float4*>(qB + (size_t)i * 32 * D_MODEL);
            }
        }
        const uint32_t* Ab = As + buf * 2048;
        const uint32_t* Bb = Bs + buf * 2048;
#pragma unroll
        for (int ks = 0; ks < 2; ++ks) {
            uint32_t af[4][4], bf[4][2];
#pragma unroll
            for (int mt = 0; mt < 4; ++mt) {
                const uint4 u = *reinterpret_cast<const uint4*>(
                    &Ab[((warp_m * 4 + mt) * 2 + ks) * 128 + lane * 4]);
                af[mt][0] = u.x; af[mt][1] = u.y; af[mt][2] = u.z; af[mt][3] = u.w;
            }
#pragma unroll
            for (int nt = 0; nt < 4; ++nt) {
                const uint2 v = *reinterpret_cast<const uint2*>(
                    &Bb[((warp_n * 4 + nt) * 2 + ks) * 64 + lane * 2]);
                bf[nt][0] = v.x; bf[nt][1] = v.y;
            }
#pragma unroll
            for (int mt = 0; mt < 4; ++mt)
#pragma unroll
                for (int nt = 0; nt < 4; ++nt)
                    mma_f16(acc[mt][nt], af[mt], bf[nt]);
        }
        if (t < 31) {
            const int ob = (buf ^ 1) * 2048;
#pragma unroll
            for (int i = 0; i < 4; ++i) {
                As[ob + sA[i]]     = packh2(ga[i].x, ga[i].y);
                As[ob + sA[i] + 4] = packh2(ga[i].z, ga[i].w);
                Bs[ob + sB[i]]     = packh2(gb[i].x, gb[i].y);
                Bs[ob + sB[i] + 2] = packh2(gb[i].z, gb[i].w);
            }
        }
        __syncthreads();
    }

    /* ------------------------------ epilogue ----------------------------- */
    const int row_q = lane >> 2;
    const int col_q = (lane & 3) * 2;

    if (head_mode) {
#pragma unroll
        for (int mt = 0; mt < 4; ++mt)
#pragma unroll
            for (int nt = 0; nt < 4; ++nt) {
                int m = m0 + warp_m * 64 + mt * 16 + row_q;
                int n = n0 + warp_n * 32 + nt * 8 + col_q;
                int h = n >> 6, dh = n & 63;
                {
                    int bb = m >> 11, l = m & 2047;
                    *reinterpret_cast<float2*>(
                        &C[(((size_t)(bb * N_HEADS + h) * L_SEQ + l) << 6) + dh])
                        = make_float2(acc[mt][nt][0], acc[mt][nt][1]);
                }
                {
                    int m2 = m + 8;
                    int bb = m2 >> 11, l = m2 & 2047;
                    *reinterpret_cast<float2*>(
                        &C[(((size_t)(bb * N_HEADS + h) * L_SEQ + l) << 6) + dh])
                        = make_float2(acc[mt][nt][2], acc[mt][nt][3]);
                }
            }
    } else {
#pragma unroll
        for (int mt = 0; mt < 4; ++mt)
#pragma unroll
            for (int nt = 0; nt < 4; ++nt) {
                int m = m0 + warp_m * 64 + mt * 16 + row_q;
                int n = n0 + warp_n * 32 + nt * 8 + col_q;
                float2 bv = *reinterpret_cast<const float2*>(&bias[n]);
                *reinterpret_cast<float2*>(&C[(size_t)m * D_MODEL + n])
                    = make_float2(acc[mt][nt][0] + bv.x, acc[mt][nt][1] + bv.y);
                *reinterpret_cast<float2*>(&C[(size_t)(m + 8) * D_MODEL + n])
                    = make_float2(acc[mt][nt][2] + bv.x, acc[mt][nt][3] + bv.y);
            }
    }
}

/* ===========================================================================
 * Euclidean flash-attention, fp16 m16n8k16, P in registers (no shuffles:
 * the S D-fragment packs directly into the fp16 A-fragment half2s).
 * 256 thr, 8 warps x 16 q-rows; 128-key tiles; two halves of 8 S-tiles.
 * w = 8*rsqrt(d2), clamp 11 (fp16-safe; normalization cancels scaling).
 * smem ~49KB, 2 CTAs/SM.
 * ========================================================================= */
#define ATT_SMEM_WORDS (4096 * 3 + 256)
#define ATT_SMEM_BYTES (ATT_SMEM_WORDS * 4)

__global__ __launch_bounds__(256, 2)
void attn_mma(const float* __restrict__ Qh, const float* __restrict__ Kh,
              const float* __restrict__ Vh, float* __restrict__ Xout)
{
    extern __shared__ __align__(16) uint32_t smw[];
    uint32_t* Qf = smw;                 /* A-frag: 8 m-tiles x 4 kk  = 4096 w */
    uint32_t* Kf = smw + 4096;          /* B-frag: 16 n-tiles x 4 kk = 4096 w */
    uint32_t* Vf = smw + 8192;          /* B-frag: 8 n-tiles x 8 kk  = 4096 w */
    float* q2 = (float*)(smw + 12288);  /* [128] */
    float* k2 = q2 + 128;               /* [128] */

    const int tid  = threadIdx.x;
    const int lane = tid & 31;
    const int wid  = tid >> 5;          /* warp owns q-rows wid*16..+15 */
    const int tq   = lane & 3;
    const int bh = blockIdx.y;
    const int q0 = blockIdx.x * 128;

    const float4* Qg4 = reinterpret_cast<const float4*>(
        Qh + ((size_t)bh * L_SEQ + q0) * D_HEAD);
    const float4* Kg4 = reinterpret_cast<const float4*>(
        Kh + (size_t)bh * L_SEQ * D_HEAD);
    const float4* Vg4 = reinterpret_cast<const float4*>(
        Vh + (size_t)bh * L_SEQ * D_HEAD);

    /* ---- prologue: Q -> Qf (fp16 A-frag) + q2 from the rounded values ---- */
#pragma unroll
    for (int it = 0; it < 8; ++it) {
        int idx = it * 256 + tid;              /* 0..2047 */
        int m = idx >> 4, c4 = idx & 15, k0 = c4 * 4;
        float4 qv = Qg4[idx];
        uint32_t h1 = packh2(qv.x, qv.y);
        uint32_t h2 = packh2(qv.z, qv.w);
        int blk = (m >> 4) * 4 + (k0 >> 4);
        int swz = (k0 >> 4) & 3;
        int lp  = (m & 7) * 4 + ((k0 >> 1) & 3);
        int rg  = ((k0 >> 3) & 1) * 2 + ((m >> 3) & 1);
        Qf[blk * 128 + ((lp ^ swz) * 4) + rg]       = h1;
        Qf[blk * 128 + (((lp + 1) ^ swz) * 4) + rg] = h2;
        float2 f1 = unpackh2(h1), f2 = unpackh2(h2);
        float part = f1.x * f1.x + f1.y * f1.y + f2.x * f2.x + f2.y * f2.y;
        part += __shfl_xor_sync(0xffffffffu, part, 1);
        part += __shfl_xor_sync(0xffffffffu, part, 2);
        part += __shfl_xor_sync(0xffffffffu, part, 4);
        part += __shfl_xor_sync(0xffffffffu, part, 8);
        if (c4 == 0) q2[m] = part;
    }
    __syncthreads();

    const float q2a = q2[wid * 16 + (lane >> 2)];
    const float q2b = q2[wid * 16 + 8 + (lane >> 2)];

    float oacc[8][4];
#pragma unroll
    for (int b = 0; b < 8; ++b)
#pragma unroll
        for (int c = 0; c < 4; ++c) oacc[b][c] = 0.f;
    float rsum0 = 0.f, rsum1 = 0.f;

    for (int kt = 0; kt < 16; ++kt) {
        /* ---- load K,V tile kt (fp16 frags) + k2 --------------------------- */
#pragma unroll
        for (int it = 0; it < 8; ++it) {
            int idx = it * 256 + tid;
            int r = idx >> 4, c4 = idx & 15, k0 = c4 * 4;

            /* K: B-frag element (n=r, k=k0..k0+3) */
            float4 kv = Kg4[kt * 2048 + idx];
            uint32_t h1 = packh2(kv.x, kv.y);
            uint32_t h2 = packh2(kv.z, kv.w);
            {
                int blk = (r >> 3) * 4 + (k0 >> 4);
                int sw  = ((r >> 3) ^ (k0 >> 4)) & 7;
                int lp  = (r & 7) * 4 + ((k0 >> 1) & 3);
                int rg  = (k0 >> 3) & 1;
                Kf[blk * 64 + ((lp ^ sw) * 2) + rg]       = h1;
                Kf[blk * 64 + (((lp + 1) ^ sw) * 2) + rg] = h2;
            }
            float2 f1 = unpackh2(h1), f2 = unpackh2(h2);
            float part = f1.x * f1.x + f1.y * f1.y + f2.x * f2.x + f2.y * f2.y;
            part += __shfl_xor_sync(0xffffffffu, part, 1);
            part += __shfl_xor_sync(0xffffffffu, part, 2);
            part += __shfl_xor_sync(0xffffffffu, part, 4);
            part += __shfl_xor_sync(0xffffffffu, part, 8);
            if (c4 == 0) k2[r] = part;

            /* V: seq row s=r, dh cols d0..d0+3 -> B-frag element (n=dh,k=s) */
            float4 vv = Vg4[kt * 2048 + idx];
            {
                int s = r, d0 = c4 * 4;
                int rg = (s >> 3) & 1;
                float vals[4] = { vv.x, vv.y, vv.z, vv.w };
#pragma unroll
                for (int j = 0; j < 4; ++j) {
                    int n = d0 + j;
                    int blk = (n >> 3) * 8 + (s >> 4);
                    int sw  = ((n >> 3) ^ (s >> 4)) & 7;
                    int lp  = ((n & 7) * 4 + ((s >> 1) & 3)) ^ sw;
                    reinterpret_cast<__half*>(Vf)[(blk * 64 + lp * 2 + rg) * 2 + (s & 1)]
                        = __float2half_rn(vals[j]);
                }
            }
        }
        __syncthreads();

        /* ---- two halves of 8 S-tiles each --------------------------------- */
#pragma unroll
        for (int half = 0; half < 2; ++half) {
            float sacc[8][4];
#pragma unroll
            for (int j = 0; j < 8; ++j)
#pragma unroll
                for (int c = 0; c < 4; ++c) sacc[j][c] = 0.f;

            /* S = Q.K^T : 4 k16-steps x 8 n-tiles */
#pragma unroll
            for (int kk = 0; kk < 4; ++kk) {
                uint32_t af[4];
                {
                    const uint4 u = *reinterpret_cast<const uint4*>(
                        &Qf[(wid * 4 + kk) * 128 + ((lane ^ kk) * 4)]);
                    af[0] = u.x; af[1] = u.y; af[2] = u.z; af[3] = u.w;
                }
#pragma unroll
                for (int j = 0; j < 8; ++j) {
                    int nt = half * 8 + j;
                    uint32_t bf[2];
                    const uint2 u2 = *reinterpret_cast<const uint2*>(
                        &Kf[(nt * 4 + kk) * 64 + ((lane ^ ((nt ^ kk) & 7)) * 2)]);
                    bf[0] = u2.x; bf[1] = u2.y;
                    mma_f16(sacc[j], af, bf);
                }
            }

            /* euclid weights -> fp16 A-fragments (no shuffles needed) */
            uint32_t pa[16];
#pragma unroll
            for (int j = 0; j < 8; ++j) {
                int nt = half * 8 + j;
                float2 k2v = *reinterpret_cast<const float2*>(&k2[nt * 8 + tq * 2]);
                float d0 = fmaxf(fmaf(sacc[j][0], -2.f, q2a + k2v.x), 1e-24f);
                float d1 = fmaxf(fmaf(sacc[j][1], -2.f, q2a + k2v.y), 1e-24f);
                float d2 = fmaxf(fmaf(sacc[j][2], -2.f, q2b + k2v.x), 1e-24f);
                float d3 = fmaxf(fmaf(sacc[j][3], -2.f, q2b + k2v.y), 1e-24f);
                float p0 = __expf(fminf(rsqrtf(d0) * 8.f, 11.f));
                float p1 = __expf(fminf(rsqrtf(d1) * 8.f, 11.f));
                float p2 = __expf(fminf(rsqrtf(d2) * 8.f, 11.f));
                float p3 = __expf(fminf(rsqrtf(d3) * 8.f, 11.f));
                rsum0 += p0 + p1;
                rsum1 += p2 + p3;
                int kkl = j >> 1, o = (j & 1) * 2;
                pa[kkl * 4 + o]     = packh2(p0, p1);   /* row g   cols 2t,2t+1 */
                pa[kkl * 4 + o + 1] = packh2(p2, p3);   /* row g+8 cols 2t,2t+1 */
            }

            /* O += P.V : 4 k16-steps (this half's 64 keys) x 8 dh-tiles */
#pragma unroll
            for (int kkl = 0; kkl < 4; ++kkl) {
                int kkg = half * 4 + kkl;
#pragma unroll
                for (int nt2 = 0; nt2 < 8; ++nt2) {
                    uint32_t bf[2];
                    const uint2 u2 = *reinterpret_cast<const uint2*>(
                        &Vf[(nt2 * 8 + kkg) * 64 + ((lane ^ ((nt2 ^ kkg) & 7)) * 2)]);
                    bf[0] = u2.x; bf[1] = u2.y;
                    mma_f16(oacc[nt2], &pa[kkl * 4], bf);
                }
            }
        }
        __syncthreads();
    }

    /* ---- quad-reduce row sums, normalize, write back ----------------------- */
    float r0 = rsum0, r1 = rsum1;
    r0 += __shfl_xor_sync(0xffffffffu, r0, 1);
    r0 += __shfl_xor_sync(0xffffffffu, r0, 2);
    r1 += __shfl_xor_sync(0xffffffffu, r1, 1);
    r1 += __shfl_xor_sync(0xffffffffu, r1, 2);
    const float inv1 = __fdividef(1.f, r0);
    const float inv2 = __fdividef(1.f, r1);

    const int b = bh >> 4, h = bh & 15;
    const int mrow = q0 + wid * 16 + (lane >> 2);
#pragma unroll
    for (int nt2 = 0; nt2 < 8; ++nt2) {
        int c = nt2 * 8 + tq * 2;
        size_t b1 = ((size_t)(b * L_SEQ + mrow)) * D_MODEL + h * 64 + c;
        size_t b2 = ((size_t)(b * L_SEQ + mrow + 8)) * D_MODEL + h * 64 + c;
        *reinterpret_cast<float2*>(&Xout[b1])
            = make_float2(oacc[nt2][0] * inv1, oacc[nt2][1] * inv1);
        *reinterpret_cast<float2*>(&Xout[b2])
            = make_float2(oacc[nt2][2] * inv2, oacc[nt2][3] * inv2);
    }
}

/* ========================================================================= */
extern "C" void kernel_launch(void* const* d_in, const int* in_sizes, int n_in,
                              void* d_out, int out_size)
{
    (void)in_sizes; (void)n_in; (void)out_size;
    const float* query = (const float*)d_in[0];
    const float* key_  = (const float*)d_in[1];
    const float* value = (const float*)d_in[2];
    const float* Wq    = (const float*)d_in[3];
    const float* Wk    = (const float*)d_in[4];
    const float* Wv    = (const float*)d_in[5];
    const float* Wo    = (const float*)d_in[6];
    const float* bo    = (const float*)d_in[7];
    float* out = (float*)d_out;

    float *qp, *kp, *vp, *xp;
    cudaGetSymbolAddress((void**)&qp, g_q);
    cudaGetSymbolAddress((void**)&kp, g_k);
    cudaGetSymbolAddress((void**)&vp, g_v);
    cudaGetSymbolAddress((void**)&xp, g_x);

    cudaFuncSetAttribute(gemm_mma, cudaFuncAttributeMaxDynamicSharedMemorySize,
                         GEMM_SMEM_BYTES);
    cudaFuncSetAttribute(attn_mma, cudaFuncAttributeMaxDynamicSharedMemorySize,
                         ATT_SMEM_BYTES);

    dim3 ggrid(D_MODEL / 128, M_ROWS / 128);
    gemm_mma<<<ggrid, 256, GEMM_SMEM_BYTES>>>(query, Wq, qp, nullptr, 1);
    gemm_mma<<<ggrid, 256, GEMM_SMEM_BYTES>>>(key_,  Wk, kp, nullptr, 1);
    gemm_mma<<<ggrid, 256, GEMM_SMEM_BYTES>>>(value, Wv, vp, nullptr, 1);

    attn_mma<<<dim3(16, BH), 256, ATT_SMEM_BYTES>>>(qp, kp, vp, xp);

    gemm_mma<<<ggrid, 256, GEMM_SMEM_BYTES>>>(xp, Wo, out, bo, 0);
}

// round 10
// speedup vs baseline: 3.0219x; 1.1701x over previous
#include <cuda_runtime.h>
#include <cuda_fp16.h>
#include <math.h>
#include <stdint.h>

#define L_SEQ   2048
#define D_MODEL 1024
#define N_HEADS 16
#define D_HEAD  64
#define BATCH   2
#define BH      (BATCH * N_HEADS)     /* 32  */
#define M_ROWS  (BATCH * L_SEQ)       /* 4096 */
#define NROWS_H (BH * L_SEQ)          /* 65536 head-rows */

/* ------------ scratch (static device globals: no allocation allowed) ------ */
__device__ __align__(16) __half g_qh[NROWS_H * D_HEAD];
__device__ __align__(16) __half g_kh[NROWS_H * D_HEAD];
__device__ __align__(16) __half g_vh[NROWS_H * D_HEAD];
__device__ __align__(16) float  g_q2[NROWS_H];
__device__ __align__(16) float  g_k2[NROWS_H];
__device__ __align__(16) float  g_x[(size_t)M_ROWS * D_MODEL];

/* =========================== helpers ===================================== */
__device__ __forceinline__ uint32_t smem_u32(const void* p)
{
    uint32_t a;
    asm("{ .reg .u64 t; cvta.to.shared.u64 t, %1; cvt.u32.u64 %0, t; }"
        : "=r"(a) : "l"(p));
    return a;
}

__device__ __forceinline__ void cp_async16(uint32_t dst, const void* src)
{
    asm volatile("cp.async.cg.shared.global [%0], [%1], 16;"
                 :: "r"(dst), "l"(src) : "memory");
}
__device__ __forceinline__ void cp_commit()
{
    asm volatile("cp.async.commit_group;" ::: "memory");
}
__device__ __forceinline__ void cp_wait1()
{
    asm volatile("cp.async.wait_group 1;" ::: "memory");
}

__device__ __forceinline__ uint32_t packh2(float lo, float hi)
{
    __half2 h = __floats2half2_rn(lo, hi);
    return *reinterpret_cast<uint32_t*>(&h);
}

__device__ __forceinline__ void mma_f16(float* d, const uint32_t* a, const uint32_t* b)
{
    asm volatile(
        "mma.sync.aligned.m16n8k16.row.col.f32.f16.f16.f32 "
        "{%0,%1,%2,%3}, {%4,%5,%6,%7}, {%8,%9}, {%0,%1,%2,%3};"
        : "+f"(d[0]), "+f"(d[1]), "+f"(d[2]), "+f"(d[3])
        : "r"(a[0]), "r"(a[1]), "r"(a[2]), "r"(a[3]),
          "r"(b[0]), "r"(b[1]));
}

__device__ __forceinline__ void ldsm_x4(uint32_t& r0, uint32_t& r1,
                                        uint32_t& r2, uint32_t& r3, uint32_t addr)
{
    asm volatile("ldmatrix.sync.aligned.m8n8.x4.shared.b16 {%0,%1,%2,%3}, [%4];"
                 : "=r"(r0), "=r"(r1), "=r"(r2), "=r"(r3) : "r"(addr));
}
__device__ __forceinline__ void ldsm_x4t(uint32_t& r0, uint32_t& r1,
                                         uint32_t& r2, uint32_t& r3, uint32_t addr)
{
    asm volatile("ldmatrix.sync.aligned.m8n8.x4.trans.shared.b16 {%0,%1,%2,%3}, [%4];"
                 : "=r"(r0), "=r"(r1), "=r"(r2), "=r"(r3) : "r"(addr));
}

/* swizzled tile: 128 rows x 64 halfs (8 x 16B units per row).
 * 16B-unit index u(r,c16) = r*8 + (c16 ^ (r&7)); byte = u*16.                */
__device__ __forceinline__ uint32_t tile_off(int r, int c16)
{
    return (uint32_t)(r * 8 + (c16 ^ (r & 7))) * 16u;
}

/* ===========================================================================
 * fp16 GEMM (R9, passing): C = A @ W^T (+bias). head_mode=1 writes __half
 * into [B,H,L,Dh]; head_mode=0 writes fp32 row-major + bias.
 * ========================================================================= */
#define GEMM_SMEM_BYTES 32768

__global__ __launch_bounds__(256)
void gemm_mma(const float* __restrict__ A, const float* __restrict__ W,
              float* __restrict__ C, const float* __restrict__ bias,
              int head_mode)
{
    extern __shared__ __align__(16) uint32_t smg[];
    uint32_t* As = smg;           /* [2][2048] */
    uint32_t* Bs = smg + 4096;    /* [2][2048] */

    const int tid = threadIdx.x;
    const int lane = tid & 31;
    const int wid = tid >> 5;
    const int warp_m = wid >> 2;
    const int warp_n = wid & 3;
    const int m0 = blockIdx.y * 128, n0 = blockIdx.x * 128;

    const int cc = tid & 7;
    const int r0 = tid >> 3;
    const int k0c = cc * 4;

    int sA[4], sB[4];
#pragma unroll
    for (int i = 0; i < 4; ++i) {
        int rr = r0 + 32 * i;
        sA[i] = ((rr >> 4) * 2 + (k0c >> 4)) * 128
              + ((rr & 7) * 4 + ((k0c >> 1) & 3)) * 4
              + ((k0c >> 3) & 1) * 2 + ((rr >> 3) & 1);
        sB[i] = ((rr >> 3) * 2 + (k0c >> 4)) * 64
              + ((rr & 7) * 4 + ((k0c >> 1) & 3)) * 2
              + ((k0c >> 3) & 1);
    }

    float acc[4][4][4];
#pragma unroll
    for (int a = 0; a < 4; ++a)
#pragma unroll
        for (int b = 0; b < 4; ++b)
#pragma unroll
            for (int c = 0; c < 4; ++c) acc[a][b][c] = 0.f;

    const float* pA = A + (size_t)(m0 + r0) * D_MODEL + k0c;
    const float* pB = W + (size_t)(n0 + r0) * D_MODEL + k0c;

    float4 ga[4], gb[4];
#pragma unroll
    for (int i = 0; i < 4; ++i) {
        ga[i] = *reinterpret_cast<const float4*>(pA + (size_t)i * 32 * D_MODEL);
        gb[i] = *reinterpret_cast<const float4*>(pB + (size_t)i * 32 * D_MODEL);
    }
#pragma unroll
    for (int i = 0; i < 4; ++i) {
        As[sA[i]]     = packh2(ga[i].x, ga[i].y);
        As[sA[i] + 4] = packh2(ga[i].z, ga[i].w);
        Bs[sB[i]]     = packh2(gb[i].x, gb[i].y);
        Bs[sB[i] + 2] = packh2(gb[i].z, gb[i].w);
    }
    __syncthreads();

    for (int t = 0; t < 32; ++t) {
        const int buf = t & 1;
        if (t < 31) {
            const float* qA = pA + (t + 1) * 32;
            const float* qB = pB + (t + 1) * 32;
#pragma unroll
            for (int i = 0; i < 4; ++i) {
                ga[i] = *reinterpret_cast<const float4*>(qA + (size_t)i * 32 * D_MODEL);
                gb[i] = *reinterpret_cast<const float4*>(qB + (size_t)i * 32 * D_MODEL);
            }
        }
        const uint32_t* Ab = As + buf * 2048;
        const uint32_t* Bb = Bs + buf * 2048;
#pragma unroll
        for (int ks = 0; ks < 2; ++ks) {
            uint32_t af[4][4], bf[4][2];
#pragma unroll
            for (int mt = 0; mt < 4; ++mt) {
                const uint4 u = *reinterpret_cast<const uint4*>(
                    &Ab[((warp_m * 4 + mt) * 2 + ks) * 128 + lane * 4]);
                af[mt][0] = u.x; af[mt][1] = u.y; af[mt][2] = u.z; af[mt][3] = u.w;
            }
#pragma unroll
            for (int nt = 0; nt < 4; ++nt) {
                const uint2 v = *reinterpret_cast<const uint2*>(
                    &Bb[((warp_n * 4 + nt) * 2 + ks) * 64 + lane * 2]);
                bf[nt][0] = v.x; bf[nt][1] = v.y;
            }
#pragma unroll
            for (int mt = 0; mt < 4; ++mt)
#pragma unroll
                for (int nt = 0; nt < 4; ++nt)
                    mma_f16(acc[mt][nt], af[mt], bf[nt]);
        }
        if (t < 31) {
            const int ob = (buf ^ 1) * 2048;
#pragma unroll
            for (int i = 0; i < 4; ++i) {
                As[ob + sA[i]]     = packh2(ga[i].x, ga[i].y);
                As[ob + sA[i] + 4] = packh2(ga[i].z, ga[i].w);
                Bs[ob + sB[i]]     = packh2(gb[i].x, gb[i].y);
                Bs[ob + sB[i] + 2] = packh2(gb[i].z, gb[i].w);
            }
        }
        __syncthreads();
    }

    /* ------------------------------ epilogue ----------------------------- */
    const int row_q = lane >> 2;
    const int col_q = (lane & 3) * 2;

    if (head_mode) {
        __half* Ch = reinterpret_cast<__half*>(C);
#pragma unroll
        for (int mt = 0; mt < 4; ++mt)
#pragma unroll
            for (int nt = 0; nt < 4; ++nt) {
                int m = m0 + warp_m * 64 + mt * 16 + row_q;
                int n = n0 + warp_n * 32 + nt * 8 + col_q;
                int h = n >> 6, dh = n & 63;
                {
                    int bb = m >> 11, l = m & 2047;
                    *reinterpret_cast<__half2*>(
                        &Ch[(((size_t)(bb * N_HEADS + h) * L_SEQ + l) << 6) + dh])
                        = __floats2half2_rn(acc[mt][nt][0], acc[mt][nt][1]);
                }
                {
                    int m2 = m + 8;
                    int bb = m2 >> 11, l = m2 & 2047;
                    *reinterpret_cast<__half2*>(
                        &Ch[(((size_t)(bb * N_HEADS + h) * L_SEQ + l) << 6) + dh])
                        = __floats2half2_rn(acc[mt][nt][2], acc[mt][nt][3]);
                }
            }
    } else {
#pragma unroll
        for (int mt = 0; mt < 4; ++mt)
#pragma unroll
            for (int nt = 0; nt < 4; ++nt) {
                int m = m0 + warp_m * 64 + mt * 16 + row_q;
                int n = n0 + warp_n * 32 + nt * 8 + col_q;
                float2 bv = *reinterpret_cast<const float2*>(&bias[n]);
                *reinterpret_cast<float2*>(&C[(size_t)m * D_MODEL + n])
                    = make_float2(acc[mt][nt][0] + bv.x, acc[mt][nt][1] + bv.y);
                *reinterpret_cast<float2*>(&C[(size_t)(m + 8) * D_MODEL + n])
                    = make_float2(acc[mt][nt][2] + bv.x, acc[mt][nt][3] + bv.y);
            }
    }
}

/* ===========================================================================
 * Row sum-of-squares: dst[r] = sum_d src[r][d]^2 over D_HEAD=64 fp16 values.
 * 8 lanes per row, 4 rows per warp. Grid covers NROWS_H exactly.
 * ========================================================================= */
__global__ __launch_bounds__(256)
void sumsq_rows(const __half* __restrict__ src, float* __restrict__ dst)
{
    int gw = (blockIdx.x * blockDim.x + threadIdx.x) >> 5;
    int lane = threadIdx.x & 31;
    int r = gw * 4 + (lane >> 3);
    const uint4 u = *reinterpret_cast<const uint4*>(
        src + (size_t)r * D_HEAD + (lane & 7) * 8);
    const __half2* h = reinterpret_cast<const __half2*>(&u);
    float s = 0.f;
#pragma unroll
    for (int i = 0; i < 4; ++i) {
        float2 f = __half22float2(h[i]);
        s += f.x * f.x + f.y * f.y;
    }
    s += __shfl_xor_sync(0xffffffffu, s, 1);
    s += __shfl_xor_sync(0xffffffffu, s, 2);
    s += __shfl_xor_sync(0xffffffffu, s, 4);
    if ((lane & 7) == 0) dst[r] = s;
}

/* ===========================================================================
 * Euclidean flash-attention: fp16 in gmem, cp.async double-buffered K/V,
 * ldmatrix fragment loads (Q A-frags persistent in registers, V via .trans),
 * precomputed q2/k2, P in registers. 256 thr, 8 warps x 16 q-rows,
 * smem 88KB -> 2 CTAs/SM.
 * ========================================================================= */
#define OFF_Q  0
#define OFF_K  16384
#define OFF_V  49152
#define OFF_K2 81920
#define ATT_SMEM_BYTES (81920 + 8192)

__global__ __launch_bounds__(256, 2)
void attn_mma(const __half* __restrict__ Qh, const __half* __restrict__ Kh,
              const __half* __restrict__ Vh, const float* __restrict__ q2g,
              const float* __restrict__ k2g, float* __restrict__ Xout)
{
    extern __shared__ __align__(16) char smc[];
    const uint32_t smB = smem_u32(smc);
    const uint32_t qB  = smB + OFF_Q;
    const uint32_t kB  = smB + OFF_K;
    const uint32_t vB  = smB + OFF_V;
    const uint32_t k2B = smB + OFF_K2;
    const float* k2s = reinterpret_cast<const float*>(smc + OFF_K2);

    const int tid  = threadIdx.x;
    const int lane = tid & 31;
    const int wid  = tid >> 5;
    const int tq   = lane & 3;
    const int lsub = lane & 7;
    const int sel  = lane >> 3;
    const int bh = blockIdx.y;
    const int q0 = blockIdx.x * 128;

    const __half* Qg = Qh + ((size_t)bh * L_SEQ + q0) * D_HEAD;
    const __half* Kg = Kh + (size_t)bh * L_SEQ * D_HEAD;
    const __half* Vg = Vh + (size_t)bh * L_SEQ * D_HEAD;

    const int lr = tid >> 3;      /* load row base (0..31), rows lr+32i */
    const int lc = tid & 7;       /* 16B chunk within row                */

    /* group 0: Q tile + whole-head k2 + K/V tile 0 */
#pragma unroll
    for (int i = 0; i < 4; ++i) {
        int r = lr + 32 * i;
        uint32_t du = tile_off(r, lc);
        cp_async16(qB + du, Qg + r * D_HEAD + lc * 8);
        cp_async16(kB + du, Kg + r * D_HEAD + lc * 8);
        cp_async16(vB + du, Vg + r * D_HEAD + lc * 8);
    }
#pragma unroll
    for (int i = 0; i < 2; ++i) {
        int j = tid + 256 * i;
        cp_async16(k2B + j * 16, k2g + (size_t)bh * L_SEQ + j * 4);
    }
    cp_commit();
    /* group 1: K/V tile 1 */
#pragma unroll
    for (int i = 0; i < 4; ++i) {
        int r = lr + 32 * i;
        uint32_t du = tile_off(r, lc);
        cp_async16(kB + 16384 + du, Kg + 8192 + r * D_HEAD + lc * 8);
        cp_async16(vB + 16384 + du, Vg + 8192 + r * D_HEAD + lc * 8);
    }
    cp_commit();

    const float q2a = q2g[(size_t)bh * L_SEQ + q0 + wid * 16 + (lane >> 2)];
    const float q2b = q2g[(size_t)bh * L_SEQ + q0 + wid * 16 + 8 + (lane >> 2)];

    cp_wait1();
    __syncthreads();

    /* persistent Q A-fragments (rows wid*16..+15, k=0..63) */
    uint32_t af[4][4];
#pragma unroll
    for (int kk = 0; kk < 4; ++kk) {
        int r = wid * 16 + (sel & 1) * 8 + lsub;
        int c = 2 * kk + (sel >> 1);
        ldsm_x4(af[kk][0], af[kk][1], af[kk][2], af[kk][3], qB + tile_off(r, c));
    }

    float oacc[8][4];
#pragma unroll
    for (int b = 0; b < 8; ++b)
#pragma unroll
        for (int c = 0; c < 4; ++c) oacc[b][c] = 0.f;
    float rsum0 = 0.f, rsum1 = 0.f;

    for (int kt = 0; kt < 16; ++kt) {
        cp_wait1();
        __syncthreads();
        const uint32_t kT = kB + (uint32_t)(kt & 1) * 16384u;
        const uint32_t vT = vB + (uint32_t)(kt & 1) * 16384u;

#pragma unroll
        for (int half = 0; half < 2; ++half) {
            float sacc[8][4];
#pragma unroll
            for (int j = 0; j < 8; ++j)
#pragma unroll
                for (int c = 0; c < 4; ++c) sacc[j][c] = 0.f;

            /* S = Q.K^T : 4 k16-steps x 4 ldmatrix pairs (8 n-tiles) */
#pragma unroll
            for (int kk = 0; kk < 4; ++kk) {
#pragma unroll
                for (int p = 0; p < 4; ++p) {
                    int ntb = half * 8 + 2 * p;
                    int r = (ntb + (sel >> 1)) * 8 + lsub;
                    int c = 2 * kk + (sel & 1);
                    uint32_t bf[4];
                    ldsm_x4(bf[0], bf[1], bf[2], bf[3], kT + tile_off(r, c));
                    mma_f16(sacc[2 * p],     af[kk], &bf[0]);
                    mma_f16(sacc[2 * p + 1], af[kk], &bf[2]);
                }
            }

            /* euclid weights -> fp16 A-fragments (direct pack, no shuffles) */
            uint32_t pa[16];
#pragma unroll
            for (int j = 0; j < 8; ++j) {
                int ky = kt * 128 + half * 64 + j * 8 + tq * 2;
                float2 k2v = *reinterpret_cast<const float2*>(&k2s[ky]);
                float d0 = fmaxf(fmaf(sacc[j][0], -2.f, q2a + k2v.x), 1e-24f);
                float d1 = fmaxf(fmaf(sacc[j][1], -2.f, q2a + k2v.y), 1e-24f);
                float d2 = fmaxf(fmaf(sacc[j][2], -2.f, q2b + k2v.x), 1e-24f);
                float d3 = fmaxf(fmaf(sacc[j][3], -2.f, q2b + k2v.y), 1e-24f);
                float p0 = __expf(fminf(rsqrtf(d0) * 8.f, 11.f));
                float p1 = __expf(fminf(rsqrtf(d1) * 8.f, 11.f));
                float p2 = __expf(fminf(rsqrtf(d2) * 8.f, 11.f));
                float p3 = __expf(fminf(rsqrtf(d3) * 8.f, 11.f));
                rsum0 += p0 + p1;
                rsum1 += p2 + p3;
                int kkl = j >> 1, o = (j & 1) * 2;
                pa[kkl * 4 + o]     = packh2(p0, p1);
                pa[kkl * 4 + o + 1] = packh2(p2, p3);
            }

            /* O += P.V : 4 k16-steps x 4 ldmatrix.trans pairs (8 dh-tiles) */
#pragma unroll
            for (int kkl = 0; kkl < 4; ++kkl) {
                int kks = half * 4 + kkl;
#pragma unroll
                for (int pd = 0; pd < 4; ++pd) {
                    int r = 16 * kks + (sel & 1) * 8 + lsub;
                    int c = 2 * pd + (sel >> 1);
                    uint32_t bf[4];
                    ldsm_x4t(bf[0], bf[1], bf[2], bf[3], vT + tile_off(r, c));
                    mma_f16(oacc[2 * pd],     &pa[kkl * 4], &bf[0]);
                    mma_f16(oacc[2 * pd + 1], &pa[kkl * 4], &bf[2]);
                }
            }
        }
        __syncthreads();

        /* prefetch tile kt+2 into the buffer just consumed */
        if (kt + 2 < 16) {
            const __half* Ks = Kg + (size_t)(kt + 2) * 8192;
            const __half* Vs = Vg + (size_t)(kt + 2) * 8192;
            const uint32_t kb = kB + (uint32_t)(kt & 1) * 16384u;
            const uint32_t vb = vB + (uint32_t)(kt & 1) * 16384u;
#pragma unroll
            for (int i = 0; i < 4; ++i) {
                int r = lr + 32 * i;
                uint32_t du = tile_off(r, lc);
                cp_async16(kb + du, Ks + r * D_HEAD + lc * 8);
                cp_async16(vb + du, Vs + r * D_HEAD + lc * 8);
            }
        }
        cp_commit();   /* empty group when nothing issued keeps counting uniform */
    }

    /* ---- quad-reduce row sums, normalize, write back ----------------------- */
    float r0 = rsum0, r1 = rsum1;
    r0 += __shfl_xor_sync(0xffffffffu, r0, 1);
    r0 += __shfl_xor_sync(0xffffffffu, r0, 2);
    r1 += __shfl_xor_sync(0xffffffffu, r1, 1);
    r1 += __shfl_xor_sync(0xffffffffu, r1, 2);
    const float inv1 = __fdividef(1.f, r0);
    const float inv2 = __fdividef(1.f, r1);

    const int b = bh >> 4, h = bh & 15;
    const int mrow = q0 + wid * 16 + (lane >> 2);
#pragma unroll
    for (int nt2 = 0; nt2 < 8; ++nt2) {
        int c = nt2 * 8 + tq * 2;
        size_t b1 = ((size_t)(b * L_SEQ + mrow)) * D_MODEL + h * 64 + c;
        size_t b2 = ((size_t)(b * L_SEQ + mrow + 8)) * D_MODEL + h * 64 + c;
        *reinterpret_cast<float2*>(&Xout[b1])
            = make_float2(oacc[nt2][0] * inv1, oacc[nt2][1] * inv1);
        *reinterpret_cast<float2*>(&Xout[b2])
            = make_float2(oacc[nt2][2] * inv2, oacc[nt2][3] * inv2);
    }
}

/* ========================================================================= */
extern "C" void kernel_launch(void* const* d_in, const int* in_sizes, int n_in,
                              void* d_out, int out_size)
{
    (void)in_sizes; (void)n_in; (void)out_size;
    const float* query = (const float*)d_in[0];
    const float* key_  = (const float*)d_in[1];
    const float* value = (const float*)d_in[2];
    const float* Wq    = (const float*)d_in[3];
    const float* Wk    = (const float*)d_in[4];
    const float* Wv    = (const float*)d_in[5];
    const float* Wo    = (const float*)d_in[6];
    const float* bo    = (const float*)d_in[7];
    float* out = (float*)d_out;

    __half *qh, *kh, *vh;
    float *q2, *k2, *xp;
    cudaGetSymbolAddress((void**)&qh, g_qh);
    cudaGetSymbolAddress((void**)&kh, g_kh);
    cudaGetSymbolAddress((void**)&vh, g_vh);
    cudaGetSymbolAddress((void**)&q2, g_q2);
    cudaGetSymbolAddress((void**)&k2, g_k2);
    cudaGetSymbolAddress((void**)&xp, g_x);

    cudaFuncSetAttribute(gemm_mma, cudaFuncAttributeMaxDynamicSharedMemorySize,
                         GEMM_SMEM_BYTES);
    cudaFuncSetAttribute(attn_mma, cudaFuncAttributeMaxDynamicSharedMemorySize,
                         ATT_SMEM_BYTES);

    dim3 ggrid(D_MODEL / 128, M_ROWS / 128);
    gemm_mma<<<ggrid, 256, GEMM_SMEM_BYTES>>>(query, Wq, (float*)qh, nullptr, 1);
    gemm_mma<<<ggrid, 256, GEMM_SMEM_BYTES>>>(key_,  Wk, (float*)kh, nullptr, 1);
    gemm_mma<<<ggrid, 256, GEMM_SMEM_BYTES>>>(value, Wv, (float*)vh, nullptr, 1);

    sumsq_rows<<<NROWS_H / 32, 256>>>(qh, q2);
    sumsq_rows<<<NROWS_H / 32, 256>>>(kh, k2);

    attn_mma<<<dim3(16, BH), 256, ATT_SMEM_BYTES>>>(qh, kh, vh, q2, k2, xp);

    gemm_mma<<<ggrid, 256, GEMM_SMEM_BYTES>>>(xp, Wo, out, bo, 0);
}

// round 11
// speedup vs baseline: 3.6520x; 1.2085x over previous
#include <cuda_runtime.h>
#include <cuda_fp16.h>
#include <math.h>
#include <stdint.h>

#define L_SEQ   2048
#define D_MODEL 1024
#define N_HEADS 16
#define D_HEAD  64
#define BATCH   2
#define BH      (BATCH * N_HEADS)     /* 32  */
#define M_ROWS  (BATCH * L_SEQ)       /* 4096 */
#define NROWS_H (BH * L_SEQ)          /* 65536 head-rows */
#define SEG_IN  (M_ROWS * D_MODEL)    /* 4M  */
#define SEG_W   (D_MODEL * D_MODEL)   /* 1M  */

/* ------------ scratch (static device globals: no allocation allowed) ------ */
__device__ __align__(16) __half g_ih[3][SEG_IN];   /* query/key/value fp16  */
__device__ __align__(16) __half g_wh[4][SEG_W];    /* Wq Wk Wv Wo fp16      */
__device__ __align__(16) __half g_qh[NROWS_H * D_HEAD];
__device__ __align__(16) __half g_kh[NROWS_H * D_HEAD];
__device__ __align__(16) __half g_vh[NROWS_H * D_HEAD];
__device__ __align__(16) float  g_q2[NROWS_H];
__device__ __align__(16) float  g_k2[NROWS_H];
__device__ __align__(16) __half g_xh[(size_t)M_ROWS * D_MODEL];

/* =========================== helpers ===================================== */
__device__ __forceinline__ uint32_t smem_u32(const void* p)
{
    uint32_t a;
    asm("{ .reg .u64 t; cvta.to.shared.u64 t, %1; cvt.u32.u64 %0, t; }"
        : "=r"(a) : "l"(p));
    return a;
}

__device__ __forceinline__ void cp_async16(uint32_t dst, const void* src)
{
    asm volatile("cp.async.cg.shared.global [%0], [%1], 16;"
                 :: "r"(dst), "l"(src) : "memory");
}
__device__ __forceinline__ void cp_commit()
{
    asm volatile("cp.async.commit_group;" ::: "memory");
}
__device__ __forceinline__ void cp_wait1()
{
    asm volatile("cp.async.wait_group 1;" ::: "memory");
}

__device__ __forceinline__ uint32_t packh2(float lo, float hi)
{
    __half2 h = __floats2half2_rn(lo, hi);
    return *reinterpret_cast<uint32_t*>(&h);
}

__device__ __forceinline__ void mma_f16(float* d, const uint32_t* a, const uint32_t* b)
{
    asm volatile(
        "mma.sync.aligned.m16n8k16.row.col.f32.f16.f16.f32 "
        "{%0,%1,%2,%3}, {%4,%5,%6,%7}, {%8,%9}, {%0,%1,%2,%3};"
        : "+f"(d[0]), "+f"(d[1]), "+f"(d[2]), "+f"(d[3])
        : "r"(a[0]), "r"(a[1]), "r"(a[2]), "r"(a[3]),
          "r"(b[0]), "r"(b[1]));
}

__device__ __forceinline__ void ldsm_x4(uint32_t& r0, uint32_t& r1,
                                        uint32_t& r2, uint32_t& r3, uint32_t addr)
{
    asm volatile("ldmatrix.sync.aligned.m8n8.x4.shared.b16 {%0,%1,%2,%3}, [%4];"
                 : "=r"(r0), "=r"(r1), "=r"(r2), "=r"(r3) : "r"(addr));
}
__device__ __forceinline__ void ldsm_x4t(uint32_t& r0, uint32_t& r1,
                                         uint32_t& r2, uint32_t& r3, uint32_t addr)
{
    asm volatile("ldmatrix.sync.aligned.m8n8.x4.trans.shared.b16 {%0,%1,%2,%3}, [%4];"
                 : "=r"(r0), "=r"(r1), "=r"(r2), "=r"(r3) : "r"(addr));
}

/* swizzled tile: rows of 64 halfs = 8 x 16B units; u(r,c16)=r*8+(c16^(r&7)) */
__device__ __forceinline__ uint32_t tile_off(int r, int c16)
{
    return (uint32_t)(r * 8 + (c16 ^ (r & 7))) * 16u;
}

/* ===========================================================================
 * fp32 -> fp16 bulk convert. grid (2048, 7): y = segment
 * (0..2 inputs of 4M elems, 3..6 weights of 1M). 8 elems/thread.
 * ========================================================================= */
__global__ __launch_bounds__(256)
void cvt_all(const float* __restrict__ q, const float* __restrict__ k,
             const float* __restrict__ v, const float* __restrict__ wq,
             const float* __restrict__ wk, const float* __restrict__ wv,
             const float* __restrict__ wo)
{
    int seg = blockIdx.y;
    size_t idx = ((size_t)blockIdx.x * 256 + threadIdx.x) * 8;
    const float* s;
    __half* d;
    if (seg < 3) {
        s = (seg == 0) ? q : (seg == 1) ? k : v;
        d = g_ih[seg];
    } else {
        if (idx >= SEG_W) return;
        int w = seg - 3;
        s = (w == 0) ? wq : (w == 1) ? wk : (w == 2) ? wv : wo;
        d = g_wh[w];
    }
    float4 f0 = *reinterpret_cast<const float4*>(s + idx);
    float4 f1 = *reinterpret_cast<const float4*>(s + idx + 4);
    uint4 o;
    o.x = packh2(f0.x, f0.y); o.y = packh2(f0.z, f0.w);
    o.z = packh2(f1.x, f1.y); o.w = packh2(f1.z, f1.w);
    *reinterpret_cast<uint4*>(d + idx) = o;
}

/* ===========================================================================
 * Pure-fp16 GEMM: C = A @ W^T (+bias). cp.async 2-deep pipeline, ldmatrix.
 * 256 thr, 8 warps (2m x 4n), CTA 128x128, BK=64. blockIdx.z selects the
 * (A, C) pair (3 fused projections, or 1 for the output GEMM).
 * head_mode=1: fp16 scatter into [B,H,L,Dh]. head_mode=0: fp32 + bias.
 * ========================================================================= */
#define GEMM_SMEM_BYTES 65536

__global__ __launch_bounds__(256, 2)
void gemm_h(const __half* __restrict__ a0, const __half* __restrict__ a1,
            const __half* __restrict__ a2,
            const __half* __restrict__ w0, const __half* __restrict__ w1,
            const __half* __restrict__ w2,
            void* c0, void* c1, void* c2,
            const float* __restrict__ bias, int head_mode)
{
    extern __shared__ __align__(16) char smc[];
    const uint32_t smB = smem_u32(smc);

    const int z = blockIdx.z;
    const __half* A = (z == 0) ? a0 : (z == 1) ? a1 : a2;
    const __half* W = (z == 0) ? w0 : (z == 1) ? w1 : w2;
    void* C = (z == 0) ? c0 : (z == 1) ? c1 : c2;

    const int tid = threadIdx.x;
    const int lane = tid & 31;
    const int wid = tid >> 5;
    const int warp_m = wid >> 2;
    const int warp_n = wid & 3;
    const int lsub = lane & 7;
    const int sel  = lane >> 3;
    const int m0 = blockIdx.y * 128, n0 = blockIdx.x * 128;

    const int lr = tid >> 3;       /* rows lr + 32i          */
    const int lc = tid & 7;        /* 16B chunk within BK=64 */

    /* prologue: tiles 0 and 1 */
#pragma unroll
    for (int b = 0; b < 2; ++b) {
        const uint32_t aT = smB + (uint32_t)b * 32768u;
#pragma unroll
        for (int i = 0; i < 4; ++i) {
            int r = lr + 32 * i;
            uint32_t du = tile_off(r, lc);
            cp_async16(aT + du,          A + (size_t)(m0 + r) * D_MODEL + b * 64 + lc * 8);
            cp_async16(aT + 16384 + du,  W + (size_t)(n0 + r) * D_MODEL + b * 64 + lc * 8);
        }
        cp_commit();
    }

    float acc[4][4][4];
#pragma unroll
    for (int a = 0; a < 4; ++a)
#pragma unroll
        for (int b = 0; b < 4; ++b)
#pragma unroll
            for (int c = 0; c < 4; ++c) acc[a][b][c] = 0.f;

    for (int t = 0; t < 16; ++t) {
        cp_wait1();
        __syncthreads();
        const uint32_t aT = smB + (uint32_t)(t & 1) * 32768u;
        const uint32_t bT = aT + 16384u;

#pragma unroll
        for (int kk = 0; kk < 4; ++kk) {
            uint32_t af[4][4];
#pragma unroll
            for (int mt = 0; mt < 4; ++mt) {
                int r = warp_m * 64 + mt * 16 + (sel & 1) * 8 + lsub;
                int c = 2 * kk + (sel >> 1);
                ldsm_x4(af[mt][0], af[mt][1], af[mt][2], af[mt][3],
                        aT + tile_off(r, c));
            }
#pragma unroll
            for (int p = 0; p < 2; ++p) {
                int r = (warp_n * 4 + 2 * p + (sel >> 1)) * 8 + lsub;
                int c = 2 * kk + (sel & 1);
                uint32_t bf[4];
                ldsm_x4(bf[0], bf[1], bf[2], bf[3], bT + tile_off(r, c));
#pragma unroll
                for (int mt = 0; mt < 4; ++mt) {
                    mma_f16(acc[mt][2 * p],     af[mt], &bf[0]);
                    mma_f16(acc[mt][2 * p + 1], af[mt], &bf[2]);
                }
            }
        }
        __syncthreads();

        if (t + 2 < 16) {
            const uint32_t pT = smB + (uint32_t)(t & 1) * 32768u;
#pragma unroll
            for (int i = 0; i < 4; ++i) {
                int r = lr + 32 * i;
                uint32_t du = tile_off(r, lc);
                cp_async16(pT + du,         A + (size_t)(m0 + r) * D_MODEL + (t + 2) * 64 + lc * 8);
                cp_async16(pT + 16384 + du, W + (size_t)(n0 + r) * D_MODEL + (t + 2) * 64 + lc * 8);
            }
        }
        cp_commit();
    }

    /* ------------------------------ epilogue ----------------------------- */
    const int row_q = lane >> 2;
    const int col_q = (lane & 3) * 2;

    if (head_mode) {
        __half* Ch = reinterpret_cast<__half*>(C);
#pragma unroll
        for (int mt = 0; mt < 4; ++mt)
#pragma unroll
            for (int nt = 0; nt < 4; ++nt) {
                int m = m0 + warp_m * 64 + mt * 16 + row_q;
                int n = n0 + warp_n * 32 + nt * 8 + col_q;
                int h = n >> 6, dh = n & 63;
                {
                    int bb = m >> 11, l = m & 2047;
                    *reinterpret_cast<__half2*>(
                        &Ch[(((size_t)(bb * N_HEADS + h) * L_SEQ + l) << 6) + dh])
                        = __floats2half2_rn(acc[mt][nt][0], acc[mt][nt][1]);
                }
                {
                    int m2 = m + 8;
                    int bb = m2 >> 11, l = m2 & 2047;
                    *reinterpret_cast<__half2*>(
                        &Ch[(((size_t)(bb * N_HEADS + h) * L_SEQ + l) << 6) + dh])
                        = __floats2half2_rn(acc[mt][nt][2], acc[mt][nt][3]);
                }
            }
    } else {
        float* Cf = reinterpret_cast<float*>(C);
#pragma unroll
        for (int mt = 0; mt < 4; ++mt)
#pragma unroll
            for (int nt = 0; nt < 4; ++nt) {
                int m = m0 + warp_m * 64 + mt * 16 + row_q;
                int n = n0 + warp_n * 32 + nt * 8 + col_q;
                float2 bv = *reinterpret_cast<const float2*>(&bias[n]);
                *reinterpret_cast<float2*>(&Cf[(size_t)m * D_MODEL + n])
                    = make_float2(acc[mt][nt][0] + bv.x, acc[mt][nt][1] + bv.y);
                *reinterpret_cast<float2*>(&Cf[(size_t)(m + 8) * D_MODEL + n])
                    = make_float2(acc[mt][nt][2] + bv.x, acc[mt][nt][3] + bv.y);
            }
    }
}

/* ===========================================================================
 * Row sum-of-squares over D_HEAD=64 fp16; grid (2048, 2): y=0 -> q, y=1 -> k.
 * ========================================================================= */
__global__ __launch_bounds__(256)
void sumsq_rows()
{
    const __half* src = blockIdx.y ? g_kh : g_qh;
    float* dst = blockIdx.y ? g_k2 : g_q2;
    int gw = (blockIdx.x * 256 + threadIdx.x) >> 5;
    int lane = threadIdx.x & 31;
    int r = gw * 4 + (lane >> 3);
    const uint4 u = *reinterpret_cast<const uint4*>(
        src + (size_t)r * D_HEAD + (lane & 7) * 8);
    const __half2* h = reinterpret_cast<const __half2*>(&u);
    float s = 0.f;
#pragma unroll
    for (int i = 0; i < 4; ++i) {
        float2 f = __half22float2(h[i]);
        s += f.x * f.x + f.y * f.y;
    }
    s += __shfl_xor_sync(0xffffffffu, s, 1);
    s += __shfl_xor_sync(0xffffffffu, s, 2);
    s += __shfl_xor_sync(0xffffffffu, s, 4);
    if ((lane & 7) == 0) dst[r] = s;
}

/* ===========================================================================
 * Euclidean flash-attention (R10, passing) — output now fp16.
 * ========================================================================= */
#define OFF_Q  0
#define OFF_K  16384
#define OFF_V  49152
#define OFF_K2 81920
#define ATT_SMEM_BYTES (81920 + 8192)

__global__ __launch_bounds__(256, 2)
void attn_mma(const __half* __restrict__ Qh, const __half* __restrict__ Kh,
              const __half* __restrict__ Vh, const float* __restrict__ q2g,
              const float* __restrict__ k2g, __half* __restrict__ Xout)
{
    extern __shared__ __align__(16) char smc[];
    const uint32_t smB = smem_u32(smc);
    const uint32_t qB  = smB + OFF_Q;
    const uint32_t kB  = smB + OFF_K;
    const uint32_t vB  = smB + OFF_V;
    const uint32_t k2B = smB + OFF_K2;
    const float* k2s = reinterpret_cast<const float*>(smc + OFF_K2);

    const int tid  = threadIdx.x;
    const int lane = tid & 31;
    const int wid  = tid >> 5;
    const int tq   = lane & 3;
    const int lsub = lane & 7;
    const int sel  = lane >> 3;
    const int bh = blockIdx.y;
    const int q0 = blockIdx.x * 128;

    const __half* Qg = Qh + ((size_t)bh * L_SEQ + q0) * D_HEAD;
    const __half* Kg = Kh + (size_t)bh * L_SEQ * D_HEAD;
    const __half* Vg = Vh + (size_t)bh * L_SEQ * D_HEAD;

    const int lr = tid >> 3;
    const int lc = tid & 7;

#pragma unroll
    for (int i = 0; i < 4; ++i) {
        int r = lr + 32 * i;
        uint32_t du = tile_off(r, lc);
        cp_async16(qB + du, Qg + r * D_HEAD + lc * 8);
        cp_async16(kB + du, Kg + r * D_HEAD + lc * 8);
        cp_async16(vB + du, Vg + r * D_HEAD + lc * 8);
    }
#pragma unroll
    for (int i = 0; i < 2; ++i) {
        int j = tid + 256 * i;
        cp_async16(k2B + j * 16, k2g + (size_t)bh * L_SEQ + j * 4);
    }
    cp_commit();
#pragma unroll
    for (int i = 0; i < 4; ++i) {
        int r = lr + 32 * i;
        uint32_t du = tile_off(r, lc);
        cp_async16(kB + 16384 + du, Kg + 8192 + r * D_HEAD + lc * 8);
        cp_async16(vB + 16384 + du, Vg + 8192 + r * D_HEAD + lc * 8);
    }
    cp_commit();

    const float q2a = q2g[(size_t)bh * L_SEQ + q0 + wid * 16 + (lane >> 2)];
    const float q2b = q2g[(size_t)bh * L_SEQ + q0 + wid * 16 + 8 + (lane >> 2)];

    cp_wait1();
    __syncthreads();

    uint32_t af[4][4];
#pragma unroll
    for (int kk = 0; kk < 4; ++kk) {
        int r = wid * 16 + (sel & 1) * 8 + lsub;
        int c = 2 * kk + (sel >> 1);
        ldsm_x4(af[kk][0], af[kk][1], af[kk][2], af[kk][3], qB + tile_off(r, c));
    }

    float oacc[8][4];
#pragma unroll
    for (int b = 0; b < 8; ++b)
#pragma unroll
        for (int c = 0; c < 4; ++c) oacc[b][c] = 0.f;
    float rsum0 = 0.f, rsum1 = 0.f;

    for (int kt = 0; kt < 16; ++kt) {
        cp_wait1();
        __syncthreads();
        const uint32_t kT = kB + (uint32_t)(kt & 1) * 16384u;
        const uint32_t vT = vB + (uint32_t)(kt & 1) * 16384u;

#pragma unroll
        for (int half = 0; half < 2; ++half) {
            float sacc[8][4];
#pragma unroll
            for (int j = 0; j < 8; ++j)
#pragma unroll
                for (int c = 0; c < 4; ++c) sacc[j][c] = 0.f;

#pragma unroll
            for (int kk = 0; kk < 4; ++kk) {
#pragma unroll
                for (int p = 0; p < 4; ++p) {
                    int ntb = half * 8 + 2 * p;
                    int r = (ntb + (sel >> 1)) * 8 + lsub;
                    int c = 2 * kk + (sel & 1);
                    uint32_t bf[4];
                    ldsm_x4(bf[0], bf[1], bf[2], bf[3], kT + tile_off(r, c));
                    mma_f16(sacc[2 * p],     af[kk], &bf[0]);
                    mma_f16(sacc[2 * p + 1], af[kk], &bf[2]);
                }
            }

            uint32_t pa[16];
#pragma unroll
            for (int j = 0; j < 8; ++j) {
                int ky = kt * 128 + half * 64 + j * 8 + tq * 2;
                float2 k2v = *reinterpret_cast<const float2*>(&k2s[ky]);
                float d0 = fmaxf(fmaf(sacc[j][0], -2.f, q2a + k2v.x), 1e-24f);
                float d1 = fmaxf(fmaf(sacc[j][1], -2.f, q2a + k2v.y), 1e-24f);
                float d2 = fmaxf(fmaf(sacc[j][2], -2.f, q2b + k2v.x), 1e-24f);
                float d3 = fmaxf(fmaf(sacc[j][3], -2.f, q2b + k2v.y), 1e-24f);
                float p0 = __expf(fminf(rsqrtf(d0) * 8.f, 11.f));
                float p1 = __expf(fminf(rsqrtf(d1) * 8.f, 11.f));
                float p2 = __expf(fminf(rsqrtf(d2) * 8.f, 11.f));
                float p3 = __expf(fminf(rsqrtf(d3) * 8.f, 11.f));
                rsum0 += p0 + p1;
                rsum1 += p2 + p3;
                int kkl = j >> 1, o = (j & 1) * 2;
                pa[kkl * 4 + o]     = packh2(p0, p1);
                pa[kkl * 4 + o + 1] = packh2(p2, p3);
            }

#pragma unroll
            for (int kkl = 0; kkl < 4; ++kkl) {
                int kks = half * 4 + kkl;
#pragma unroll
                for (int pd = 0; pd < 4; ++pd) {
                    int r = 16 * kks + (sel & 1) * 8 + lsub;
                    int c = 2 * pd + (sel >> 1);
                    uint32_t bf[4];
                    ldsm_x4t(bf[0], bf[1], bf[2], bf[3], vT + tile_off(r, c));
                    mma_f16(oacc[2 * pd],     &pa[kkl * 4], &bf[0]);
                    mma_f16(oacc[2 * pd + 1], &pa[kkl * 4], &bf[2]);
                }
            }
        }
        __syncthreads();

        if (kt + 2 < 16) {
            const __half* Ks = Kg + (size_t)(kt + 2) * 8192;
            const __half* Vs = Vg + (size_t)(kt + 2) * 8192;
            const uint32_t kb = kB + (uint32_t)(kt & 1) * 16384u;
            const uint32_t vb = vB + (uint32_t)(kt & 1) * 16384u;
#pragma unroll
            for (int i = 0; i < 4; ++i) {
                int r = lr + 32 * i;
                uint32_t du = tile_off(r, lc);
                cp_async16(kb + du, Ks + r * D_HEAD + lc * 8);
                cp_async16(vb + du, Vs + r * D_HEAD + lc * 8);
            }
        }
        cp_commit();
    }

    float r0 = rsum0, r1 = rsum1;
    r0 += __shfl_xor_sync(0xffffffffu, r0, 1);
    r0 += __shfl_xor_sync(0xffffffffu, r0, 2);
    r1 += __shfl_xor_sync(0xffffffffu, r1, 1);
    r1 += __shfl_xor_sync(0xffffffffu, r1, 2);
    const float inv1 = __fdividef(1.f, r0);
    const float inv2 = __fdividef(1.f, r1);

    const int b = bh >> 4, h = bh & 15;
    const int mrow = q0 + wid * 16 + (lane >> 2);
#pragma unroll
    for (int nt2 = 0; nt2 < 8; ++nt2) {
        int c = nt2 * 8 + tq * 2;
        size_t b1 = ((size_t)(b * L_SEQ + mrow)) * D_MODEL + h * 64 + c;
        size_t b2 = ((size_t)(b * L_SEQ + mrow + 8)) * D_MODEL + h * 64 + c;
        *reinterpret_cast<__half2*>(&Xout[b1])
            = __floats2half2_rn(oacc[nt2][0] * inv1, oacc[nt2][1] * inv1);
        *reinterpret_cast<__half2*>(&Xout[b2])
            = __floats2half2_rn(oacc[nt2][2] * inv2, oacc[nt2][3] * inv2);
    }
}

/* ========================================================================= */
extern "C" void kernel_launch(void* const* d_in, const int* in_sizes, int n_in,
                              void* d_out, int out_size)
{
    (void)in_sizes; (void)n_in; (void)out_size;
    const float* query = (const float*)d_in[0];
    const float* key_  = (const float*)d_in[1];
    const float* value = (const float*)d_in[2];
    const float* Wq    = (const float*)d_in[3];
    const float* Wk    = (const float*)d_in[4];
    const float* Wv    = (const float*)d_in[5];
    const float* Wo    = (const float*)d_in[6];
    const float* bo    = (const float*)d_in[7];
    float* out = (float*)d_out;

    __half *ih, *wh, *qh, *kh, *vh, *xh;
    float *q2, *k2;
    cudaGetSymbolAddress((void**)&ih, g_ih);
    cudaGetSymbolAddress((void**)&wh, g_wh);
    cudaGetSymbolAddress((void**)&qh, g_qh);
    cudaGetSymbolAddress((void**)&kh, g_kh);
    cudaGetSymbolAddress((void**)&vh, g_vh);
    cudaGetSymbolAddress((void**)&q2, g_q2);
    cudaGetSymbolAddress((void**)&k2, g_k2);
    cudaGetSymbolAddress((void**)&xh, g_xh);

    cudaFuncSetAttribute(gemm_h, cudaFuncAttributeMaxDynamicSharedMemorySize,
                         GEMM_SMEM_BYTES);
    cudaFuncSetAttribute(attn_mma, cudaFuncAttributeMaxDynamicSharedMemorySize,
                         ATT_SMEM_BYTES);

    cvt_all<<<dim3(2048, 7), 256>>>(query, key_, value, Wq, Wk, Wv, Wo);

    /* fused q/k/v projections */
    gemm_h<<<dim3(8, 32, 3), 256, GEMM_SMEM_BYTES>>>(
        ih, ih + SEG_IN, ih + 2 * SEG_IN,
        wh, wh + SEG_W, wh + 2 * SEG_W,
        qh, kh, vh, nullptr, 1);

    sumsq_rows<<<dim3(2048, 2), 256>>>();

    attn_mma<<<dim3(16, BH), 256, ATT_SMEM_BYTES>>>(qh, kh, vh, q2, k2, xh);

    /* output projection */
    gemm_h<<<dim3(8, 32, 1), 256, GEMM_SMEM_BYTES>>>(
        xh, xh, xh, wh + 3 * SEG_W, wh + 3 * SEG_W, wh + 3 * SEG_W,
        out, out, out, bo, 0);
}

// round 12
// speedup vs baseline: 3.8466x; 1.0533x over previous
#include <cuda_runtime.h>
#include <cuda_fp16.h>
#include <math.h>
#include <stdint.h>

#define L_SEQ   2048
#define D_MODEL 1024
#define N_HEADS 16
#define D_HEAD  64
#define BATCH   2
#define BH      (BATCH * N_HEADS)     /* 32  */
#define M_ROWS  (BATCH * L_SEQ)       /* 4096 */
#define NROWS_H (BH * L_SEQ)          /* 65536 head-rows */
#define SEG_IN  (M_ROWS * D_MODEL)    /* 4M  */
#define SEG_W   (D_MODEL * D_MODEL)   /* 1M  */

/* ------------ scratch (static device globals: no allocation allowed) ------ */
__device__ __align__(16) __half g_ih[3][SEG_IN];   /* query/key/value fp16  */
__device__ __align__(16) __half g_wh[4][SEG_W];    /* Wq Wk Wv Wo fp16      */
__device__ __align__(16) __half g_qh[NROWS_H * D_HEAD];
__device__ __align__(16) __half g_kh[NROWS_H * D_HEAD];
__device__ __align__(16) __half g_vh[NROWS_H * D_HEAD];
__device__ __align__(16) float  g_q2[NROWS_H];
__device__ __align__(16) float  g_k2[NROWS_H];
__device__ __align__(16) __half g_xh[(size_t)M_ROWS * D_MODEL];

/* =========================== helpers ===================================== */
__device__ __forceinline__ uint32_t smem_u32(const void* p)
{
    uint32_t a;
    asm("{ .reg .u64 t; cvta.to.shared.u64 t, %1; cvt.u32.u64 %0, t; }"
        : "=r"(a) : "l"(p));
    return a;
}

__device__ __forceinline__ void cp_async16(uint32_t dst, const void* src)
{
    asm volatile("cp.async.cg.shared.global [%0], [%1], 16;"
                 :: "r"(dst), "l"(src) : "memory");
}
__device__ __forceinline__ void cp_commit()
{
    asm volatile("cp.async.commit_group;" ::: "memory");
}
__device__ __forceinline__ void cp_wait1()
{
    asm volatile("cp.async.wait_group 1;" ::: "memory");
}

__device__ __forceinline__ uint32_t packh2(float lo, float hi)
{
    __half2 h = __floats2half2_rn(lo, hi);
    return *reinterpret_cast<uint32_t*>(&h);
}

/* 2^w for two fp16 values at once; input packed from two floats */
__device__ __forceinline__ uint32_t ex2h2(float lo, float hi)
{
    __half2 h = __floats2half2_rn(lo, hi);
    uint32_t w = *reinterpret_cast<uint32_t*>(&h), r;
    asm("ex2.approx.f16x2 %0, %1;" : "=r"(r) : "r"(w));
    return r;
}

__device__ __forceinline__ void mma_f16(float* d, const uint32_t* a, const uint32_t* b)
{
    asm volatile(
        "mma.sync.aligned.m16n8k16.row.col.f32.f16.f16.f32 "
        "{%0,%1,%2,%3}, {%4,%5,%6,%7}, {%8,%9}, {%0,%1,%2,%3};"
        : "+f"(d[0]), "+f"(d[1]), "+f"(d[2]), "+f"(d[3])
        : "r"(a[0]), "r"(a[1]), "r"(a[2]), "r"(a[3]),
          "r"(b[0]), "r"(b[1]));
}

__device__ __forceinline__ void ldsm_x4(uint32_t& r0, uint32_t& r1,
                                        uint32_t& r2, uint32_t& r3, uint32_t addr)
{
    asm volatile("ldmatrix.sync.aligned.m8n8.x4.shared.b16 {%0,%1,%2,%3}, [%4];"
                 : "=r"(r0), "=r"(r1), "=r"(r2), "=r"(r3) : "r"(addr));
}
__device__ __forceinline__ void ldsm_x4t(uint32_t& r0, uint32_t& r1,
                                         uint32_t& r2, uint32_t& r3, uint32_t addr)
{
    asm volatile("ldmatrix.sync.aligned.m8n8.x4.trans.shared.b16 {%0,%1,%2,%3}, [%4];"
                 : "=r"(r0), "=r"(r1), "=r"(r2), "=r"(r3) : "r"(addr));
}

/* swizzled tile: rows of 64 halfs = 8 x 16B units; u(r,c16)=r*8+(c16^(r&7)) */
__device__ __forceinline__ uint32_t tile_off(int r, int c16)
{
    return (uint32_t)(r * 8 + (c16 ^ (r & 7))) * 16u;
}

/* ===========================================================================
 * fp32 -> fp16 bulk convert. grid (2048, 7).
 * ========================================================================= */
__global__ __launch_bounds__(256)
void cvt_all(const float* __restrict__ q, const float* __restrict__ k,
             const float* __restrict__ v, const float* __restrict__ wq,
             const float* __restrict__ wk, const float* __restrict__ wv,
             const float* __restrict__ wo)
{
    int seg = blockIdx.y;
    size_t idx = ((size_t)blockIdx.x * 256 + threadIdx.x) * 8;
    const float* s;
    __half* d;
    if (seg < 3) {
        s = (seg == 0) ? q : (seg == 1) ? k : v;
        d = g_ih[seg];
    } else {
        if (idx >= SEG_W) return;
        int w = seg - 3;
        s = (w == 0) ? wq : (w == 1) ? wk : (w == 2) ? wv : wo;
        d = g_wh[w];
    }
    float4 f0 = *reinterpret_cast<const float4*>(s + idx);
    float4 f1 = *reinterpret_cast<const float4*>(s + idx + 4);
    uint4 o;
    o.x = packh2(f0.x, f0.y); o.y = packh2(f0.z, f0.w);
    o.z = packh2(f1.x, f1.y); o.w = packh2(f1.z, f1.w);
    *reinterpret_cast<uint4*>(d + idx) = o;
}

/* ===========================================================================
 * Pure-fp16 GEMM (R11, passing): C = A @ W^T (+bias), cp.async + ldmatrix.
 * ========================================================================= */
#define GEMM_SMEM_BYTES 65536

__global__ __launch_bounds__(256, 2)
void gemm_h(const __half* __restrict__ a0, const __half* __restrict__ a1,
            const __half* __restrict__ a2,
            const __half* __restrict__ w0, const __half* __restrict__ w1,
            const __half* __restrict__ w2,
            void* c0, void* c1, void* c2,
            const float* __restrict__ bias, int head_mode)
{
    extern __shared__ __align__(16) char smc[];
    const uint32_t smB = smem_u32(smc);

    const int z = blockIdx.z;
    const __half* A = (z == 0) ? a0 : (z == 1) ? a1 : a2;
    const __half* W = (z == 0) ? w0 : (z == 1) ? w1 : w2;
    void* C = (z == 0) ? c0 : (z == 1) ? c1 : c2;

    const int tid = threadIdx.x;
    const int lane = tid & 31;
    const int wid = tid >> 5;
    const int warp_m = wid >> 2;
    const int warp_n = wid & 3;
    const int lsub = lane & 7;
    const int sel  = lane >> 3;
    const int m0 = blockIdx.y * 128, n0 = blockIdx.x * 128;

    const int lr = tid >> 3;
    const int lc = tid & 7;

#pragma unroll
    for (int b = 0; b < 2; ++b) {
        const uint32_t aT = smB + (uint32_t)b * 32768u;
#pragma unroll
        for (int i = 0; i < 4; ++i) {
            int r = lr + 32 * i;
            uint32_t du = tile_off(r, lc);
            cp_async16(aT + du,          A + (size_t)(m0 + r) * D_MODEL + b * 64 + lc * 8);
            cp_async16(aT + 16384 + du,  W + (size_t)(n0 + r) * D_MODEL + b * 64 + lc * 8);
        }
        cp_commit();
    }

    float acc[4][4][4];
#pragma unroll
    for (int a = 0; a < 4; ++a)
#pragma unroll
        for (int b = 0; b < 4; ++b)
#pragma unroll
            for (int c = 0; c < 4; ++c) acc[a][b][c] = 0.f;

    for (int t = 0; t < 16; ++t) {
        cp_wait1();
        __syncthreads();
        const uint32_t aT = smB + (uint32_t)(t & 1) * 32768u;
        const uint32_t bT = aT + 16384u;

#pragma unroll
        for (int kk = 0; kk < 4; ++kk) {
            uint32_t af[4][4];
#pragma unroll
            for (int mt = 0; mt < 4; ++mt) {
                int r = warp_m * 64 + mt * 16 + (sel & 1) * 8 + lsub;
                int c = 2 * kk + (sel >> 1);
                ldsm_x4(af[mt][0], af[mt][1], af[mt][2], af[mt][3],
                        aT + tile_off(r, c));
            }
#pragma unroll
            for (int p = 0; p < 2; ++p) {
                int r = (warp_n * 4 + 2 * p + (sel >> 1)) * 8 + lsub;
                int c = 2 * kk + (sel & 1);
                uint32_t bf[4];
                ldsm_x4(bf[0], bf[1], bf[2], bf[3], bT + tile_off(r, c));
#pragma unroll
                for (int mt = 0; mt < 4; ++mt) {
                    mma_f16(acc[mt][2 * p],     af[mt], &bf[0]);
                    mma_f16(acc[mt][2 * p + 1], af[mt], &bf[2]);
                }
            }
        }
        __syncthreads();

        if (t + 2 < 16) {
            const uint32_t pT = smB + (uint32_t)(t & 1) * 32768u;
#pragma unroll
            for (int i = 0; i < 4; ++i) {
                int r = lr + 32 * i;
                uint32_t du = tile_off(r, lc);
                cp_async16(pT + du,         A + (size_t)(m0 + r) * D_MODEL + (t + 2) * 64 + lc * 8);
                cp_async16(pT + 16384 + du, W + (size_t)(n0 + r) * D_MODEL + (t + 2) * 64 + lc * 8);
            }
        }
        cp_commit();
    }

    const int row_q = lane >> 2;
    const int col_q = (lane & 3) * 2;

    if (head_mode) {
        __half* Ch = reinterpret_cast<__half*>(C);
#pragma unroll
        for (int mt = 0; mt < 4; ++mt)
#pragma unroll
            for (int nt = 0; nt < 4; ++nt) {
                int m = m0 + warp_m * 64 + mt * 16 + row_q;
                int n = n0 + warp_n * 32 + nt * 8 + col_q;
                int h = n >> 6, dh = n & 63;
                {
                    int bb = m >> 11, l = m & 2047;
                    *reinterpret_cast<__half2*>(
                        &Ch[(((size_t)(bb * N_HEADS + h) * L_SEQ + l) << 6) + dh])
                        = __floats2half2_rn(acc[mt][nt][0], acc[mt][nt][1]);
                }
                {
                    int m2 = m + 8;
                    int bb = m2 >> 11, l = m2 & 2047;
                    *reinterpret_cast<__half2*>(
                        &Ch[(((size_t)(bb * N_HEADS + h) * L_SEQ + l) << 6) + dh])
                        = __floats2half2_rn(acc[mt][nt][2], acc[mt][nt][3]);
                }
            }
    } else {
        float* Cf = reinterpret_cast<float*>(C);
#pragma unroll
        for (int mt = 0; mt < 4; ++mt)
#pragma unroll
            for (int nt = 0; nt < 4; ++nt) {
                int m = m0 + warp_m * 64 + mt * 16 + row_q;
                int n = n0 + warp_n * 32 + nt * 8 + col_q;
                float2 bv = *reinterpret_cast<const float2*>(&bias[n]);
                *reinterpret_cast<float2*>(&Cf[(size_t)m * D_MODEL + n])
                    = make_float2(acc[mt][nt][0] + bv.x, acc[mt][nt][1] + bv.y);
                *reinterpret_cast<float2*>(&Cf[(size_t)(m + 8) * D_MODEL + n])
                    = make_float2(acc[mt][nt][2] + bv.x, acc[mt][nt][3] + bv.y);
            }
    }
}

/* ===========================================================================
 * Row sum-of-squares over D_HEAD=64 fp16; grid (2048, 2).
 * ========================================================================= */
__global__ __launch_bounds__(256)
void sumsq_rows()
{
    const __half* src = blockIdx.y ? g_kh : g_qh;
    float* dst = blockIdx.y ? g_k2 : g_q2;
    int gw = (blockIdx.x * 256 + threadIdx.x) >> 5;
    int lane = threadIdx.x & 31;
    int r = gw * 4 + (lane >> 3);
    const uint4 u = *reinterpret_cast<const uint4*>(
        src + (size_t)r * D_HEAD + (lane & 7) * 8);
    const __half2* h = reinterpret_cast<const __half2*>(&u);
    float s = 0.f;
#pragma unroll
    for (int i = 0; i < 4; ++i) {
        float2 f = __half22float2(h[i]);
        s += f.x * f.x + f.y * f.y;
    }
    s += __shfl_xor_sync(0xffffffffu, s, 1);
    s += __shfl_xor_sync(0xffffffffu, s, 2);
    s += __shfl_xor_sync(0xffffffffu, s, 4);
    if ((lane & 7) == 0) dst[r] = s;
}

/* ===========================================================================
 * Euclidean flash-attention. R11 structure; softmax slimmed:
 *  - single clamp d'=max(d,0.5545) (= both the d<=0 guard and the w cap)
 *  - w in exp2 domain: w2 = rsqrt(d')*11.5415603 (<=15.5, fp16-safe)
 *  - ex2.approx.f16x2 writes the P fragment directly
 *  - row sums via ones-column mma (fp32 accumulator, no shuffles)
 * ========================================================================= */
#define OFF_Q  0
#define OFF_K  16384
#define OFF_V  49152
#define OFF_K2 81920
#define ATT_SMEM_BYTES (81920 + 8192)

__global__ __launch_bounds__(256, 2)
void attn_mma(const __half* __restrict__ Qh, const __half* __restrict__ Kh,
              const __half* __restrict__ Vh, const float* __restrict__ q2g,
              const float* __restrict__ k2g, __half* __restrict__ Xout)
{
    extern __shared__ __align__(16) char smc[];
    const uint32_t smB = smem_u32(smc);
    const uint32_t qB  = smB + OFF_Q;
    const uint32_t kB  = smB + OFF_K;
    const uint32_t vB  = smB + OFF_V;
    const uint32_t k2B = smB + OFF_K2;
    const float* k2s = reinterpret_cast<const float*>(smc + OFF_K2);

    const int tid  = threadIdx.x;
    const int lane = tid & 31;
    const int wid  = tid >> 5;
    const int tq   = lane & 3;
    const int lsub = lane & 7;
    const int sel  = lane >> 3;
    const int bh = blockIdx.y;
    const int q0 = blockIdx.x * 128;

    const __half* Qg = Qh + ((size_t)bh * L_SEQ + q0) * D_HEAD;
    const __half* Kg = Kh + (size_t)bh * L_SEQ * D_HEAD;
    const __half* Vg = Vh + (size_t)bh * L_SEQ * D_HEAD;

    const int lr = tid >> 3;
    const int lc = tid & 7;

#pragma unroll
    for (int i = 0; i < 4; ++i) {
        int r = lr + 32 * i;
        uint32_t du = tile_off(r, lc);
        cp_async16(qB + du, Qg + r * D_HEAD + lc * 8);
        cp_async16(kB + du, Kg + r * D_HEAD + lc * 8);
        cp_async16(vB + du, Vg + r * D_HEAD + lc * 8);
    }
#pragma unroll
    for (int i = 0; i < 2; ++i) {
        int j = tid + 256 * i;
        cp_async16(k2B + j * 16, k2g + (size_t)bh * L_SEQ + j * 4);
    }
    cp_commit();
#pragma unroll
    for (int i = 0; i < 4; ++i) {
        int r = lr + 32 * i;
        uint32_t du = tile_off(r, lc);
        cp_async16(kB + 16384 + du, Kg + 8192 + r * D_HEAD + lc * 8);
        cp_async16(vB + 16384 + du, Vg + 8192 + r * D_HEAD + lc * 8);
    }
    cp_commit();

    const float q2a = q2g[(size_t)bh * L_SEQ + q0 + wid * 16 + (lane >> 2)];
    const float q2b = q2g[(size_t)bh * L_SEQ + q0 + wid * 16 + 8 + (lane >> 2)];

    cp_wait1();
    __syncthreads();

    uint32_t af[4][4];
#pragma unroll
    for (int kk = 0; kk < 4; ++kk) {
        int r = wid * 16 + (sel & 1) * 8 + lsub;
        int c = 2 * kk + (sel >> 1);
        ldsm_x4(af[kk][0], af[kk][1], af[kk][2], af[kk][3], qB + tile_off(r, c));
    }

    const uint32_t ones[2] = { 0x3C003C00u, 0x3C003C00u };

    float oacc[8][4];
#pragma unroll
    for (int b = 0; b < 8; ++b)
#pragma unroll
        for (int c = 0; c < 4; ++c) oacc[b][c] = 0.f;
    float racc[4] = { 0.f, 0.f, 0.f, 0.f };   /* row sums via ones-mma */

    for (int kt = 0; kt < 16; ++kt) {
        cp_wait1();
        __syncthreads();
        const uint32_t kT = kB + (uint32_t)(kt & 1) * 16384u;
        const uint32_t vT = vB + (uint32_t)(kt & 1) * 16384u;

#pragma unroll
        for (int half = 0; half < 2; ++half) {
            float sacc[8][4];
#pragma unroll
            for (int j = 0; j < 8; ++j)
#pragma unroll
                for (int c = 0; c < 4; ++c) sacc[j][c] = 0.f;

#pragma unroll
            for (int kk = 0; kk < 4; ++kk) {
#pragma unroll
                for (int p = 0; p < 4; ++p) {
                    int ntb = half * 8 + 2 * p;
                    int r = (ntb + (sel >> 1)) * 8 + lsub;
                    int c = 2 * kk + (sel & 1);
                    uint32_t bf[4];
                    ldsm_x4(bf[0], bf[1], bf[2], bf[3], kT + tile_off(r, c));
                    mma_f16(sacc[2 * p],     af[kk], &bf[0]);
                    mma_f16(sacc[2 * p + 1], af[kk], &bf[2]);
                }
            }

            /* euclid weights -> P fragment. w2 = rsqrt(d)*8/ln2 <= 15.5
             * via d' = max(d, (11.5415603/15.5)^2 = 0.5545). */
            uint32_t pa[16];
#pragma unroll
            for (int j = 0; j < 8; ++j) {
                int ky = kt * 128 + half * 64 + j * 8 + tq * 2;
                float2 k2v = *reinterpret_cast<const float2*>(&k2s[ky]);
                float d0 = fmaxf(fmaf(sacc[j][0], -2.f, q2a + k2v.x), 0.5545f);
                float d1 = fmaxf(fmaf(sacc[j][1], -2.f, q2a + k2v.y), 0.5545f);
                float d2 = fmaxf(fmaf(sacc[j][2], -2.f, q2b + k2v.x), 0.5545f);
                float d3 = fmaxf(fmaf(sacc[j][3], -2.f, q2b + k2v.y), 0.5545f);
                float w0 = rsqrtf(d0) * 11.5415603f;
                float w1 = rsqrtf(d1) * 11.5415603f;
                float w2 = rsqrtf(d2) * 11.5415603f;
                float w3 = rsqrtf(d3) * 11.5415603f;
                int kkl = j >> 1, o = (j & 1) * 2;
                pa[kkl * 4 + o]     = ex2h2(w0, w1);
                pa[kkl * 4 + o + 1] = ex2h2(w2, w3);
            }

            /* row sums: racc += P @ ones (all quad lanes get the row sum) */
#pragma unroll
            for (int kkl = 0; kkl < 4; ++kkl)
                mma_f16(racc, &pa[kkl * 4], ones);

#pragma unroll
            for (int kkl = 0; kkl < 4; ++kkl) {
                int kks = half * 4 + kkl;
#pragma unroll
                for (int pd = 0; pd < 4; ++pd) {
                    int r = 16 * kks + (sel & 1) * 8 + lsub;
                    int c = 2 * pd + (sel >> 1);
                    uint32_t bf[4];
                    ldsm_x4t(bf[0], bf[1], bf[2], bf[3], vT + tile_off(r, c));
                    mma_f16(oacc[2 * pd],     &pa[kkl * 4], &bf[0]);
                    mma_f16(oacc[2 * pd + 1], &pa[kkl * 4], &bf[2]);
                }
            }
        }
        __syncthreads();

        if (kt + 2 < 16) {
            const __half* Ks = Kg + (size_t)(kt + 2) * 8192;
            const __half* Vs = Vg + (size_t)(kt + 2) * 8192;
            const uint32_t kb = kB + (uint32_t)(kt & 1) * 16384u;
            const uint32_t vb = vB + (uint32_t)(kt & 1) * 16384u;
#pragma unroll
            for (int i = 0; i < 4; ++i) {
                int r = lr + 32 * i;
                uint32_t du = tile_off(r, lc);
                cp_async16(kb + du, Ks + r * D_HEAD + lc * 8);
                cp_async16(vb + du, Vs + r * D_HEAD + lc * 8);
            }
        }
        cp_commit();
    }

    const float inv1 = __fdividef(1.f, racc[0]);
    const float inv2 = __fdividef(1.f, racc[2]);

    const int b = bh >> 4, h = bh & 15;
    const int mrow = q0 + wid * 16 + (lane >> 2);
#pragma unroll
    for (int nt2 = 0; nt2 < 8; ++nt2) {
        int c = nt2 * 8 + tq * 2;
        size_t b1 = ((size_t)(b * L_SEQ + mrow)) * D_MODEL + h * 64 + c;
        size_t b2 = ((size_t)(b * L_SEQ + mrow + 8)) * D_MODEL + h * 64 + c;
        *reinterpret_cast<__half2*>(&Xout[b1])
            = __floats2half2_rn(oacc[nt2][0] * inv1, oacc[nt2][1] * inv1);
        *reinterpret_cast<__half2*>(&Xout[b2])
            = __floats2half2_rn(oacc[nt2][2] * inv2, oacc[nt2][3] * inv2);
    }
}

/* ========================================================================= */
extern "C" void kernel_launch(void* const* d_in, const int* in_sizes, int n_in,
                              void* d_out, int out_size)
{
    (void)in_sizes; (void)n_in; (void)out_size;
    const float* query = (const float*)d_in[0];
    const float* key_  = (const float*)d_in[1];
    const float* value = (const float*)d_in[2];
    const float* Wq    = (const float*)d_in[3];
    const float* Wk    = (const float*)d_in[4];
    const float* Wv    = (const float*)d_in[5];
    const float* Wo    = (const float*)d_in[6];
    const float* bo    = (const float*)d_in[7];
    float* out = (float*)d_out;

    __half *ih, *wh, *qh, *kh, *vh, *xh;
    float *q2, *k2;
    cudaGetSymbolAddress((void**)&ih, g_ih);
    cudaGetSymbolAddress((void**)&wh, g_wh);
    cudaGetSymbolAddress((void**)&qh, g_qh);
    cudaGetSymbolAddress((void**)&kh, g_kh);
    cudaGetSymbolAddress((void**)&vh, g_vh);
    cudaGetSymbolAddress((void**)&q2, g_q2);
    cudaGetSymbolAddress((void**)&k2, g_k2);
    cudaGetSymbolAddress((void**)&xh, g_xh);

    cudaFuncSetAttribute(gemm_h, cudaFuncAttributeMaxDynamicSharedMemorySize,
                         GEMM_SMEM_BYTES);
    cudaFuncSetAttribute(attn_mma, cudaFuncAttributeMaxDynamicSharedMemorySize,
                         ATT_SMEM_BYTES);

    cvt_all<<<dim3(2048, 7), 256>>>(query, key_, value, Wq, Wk, Wv, Wo);

    gemm_h<<<dim3(8, 32, 3), 256, GEMM_SMEM_BYTES>>>(
        ih, ih + SEG_IN, ih + 2 * SEG_IN,
        wh, wh + SEG_W, wh + 2 * SEG_W,
        qh, kh, vh, nullptr, 1);

    sumsq_rows<<<dim3(2048, 2), 256>>>();

    attn_mma<<<dim3(16, BH), 256, ATT_SMEM_BYTES>>>(qh, kh, vh, q2, k2, xh);

    gemm_h<<<dim3(8, 32, 1), 256, GEMM_SMEM_BYTES>>>(
        xh, xh, xh, wh + 3 * SEG_W, wh + 3 * SEG_W, wh + 3 * SEG_W,
        out, out, out, bo, 0);
}